// round 12
// baseline (speedup 1.0000x reference)
#include <cuda_runtime.h>
#include <cuda_fp16.h>
#include <cstdint>

// GraphConvNet: B=32, C=32, V=1024, L=13, support=3, order=2
// X column order m' = (b,l,c); yt[(g,v)][b,l,c] read directly by k_final.
// gemm1: 1-term fp16, BM=256 BN=128, 512 thr (16 warps/SM, lower smem dup).
// gemm0: (A^T)^2 exact 2-term, BM=128 BN=128, 2-stage, 2 CTAs/SM.

#define V_N   1024
#define MCOLS 13312
#define MI    6144
#define CIN   224
#define NB    32
#define PAD_E 232

// ---------------- scratch ----------------
__device__ __align__(16) __half g_yt [(size_t)MI * MCOLS];      // [i=(g,v)][m'=(b,l,c)]
__device__ __align__(16) __half g_Abf_h[(size_t)MI * V_N];
__device__ __align__(16) __half g_Abf_l[(size_t)MI * V_N];      // only rows [s*2048, s*2048+1024)
__device__ __align__(16) __half g_Bh [3u * 1024u * 1024u];
__device__ __align__(16) __half g_Xh [(size_t)MCOLS * V_N];     // [m'=(b,l,c)][v]
__device__ __align__(16) __half g_Xt [(size_t)NB * MCOLS * 32]; // [(b,v,l)][c]
__device__ __align__(16) __half g_Wh [64 * CIN];

// ================= helpers =================
__device__ __forceinline__ uint32_t smem_u32(const void* p) {
    uint32_t a;
    asm("{ .reg .u64 t; cvta.to.shared.u64 t, %1; cvt.u32.u64 %0, t; }" : "=r"(a) : "l"(p));
    return a;
}
#define CP16(s, g) asm volatile("cp.async.cg.shared.global [%0], [%1], 16;" :: "r"(s), "l"(g))
#define CP_COMMIT() asm volatile("cp.async.commit_group;")
#define CP_WAIT2()  asm volatile("cp.async.wait_group 2;")
#define CP_WAIT1()  asm volatile("cp.async.wait_group 1;")
#define CP_WAIT0()  asm volatile("cp.async.wait_group 0;")

#define LDSM4(r, addr)                                                          \
    asm volatile("ldmatrix.sync.aligned.m8n8.x4.shared.b16 {%0,%1,%2,%3}, [%4];"\
        : "=r"((r)[0]), "=r"((r)[1]), "=r"((r)[2]), "=r"((r)[3]) : "r"(addr))

#define MMAH(d, a, b0, b1)                                                      \
    asm volatile("mma.sync.aligned.m16n8k16.row.col.f32.f16.f16.f32 "           \
        "{%0,%1,%2,%3},{%4,%5,%6,%7},{%8,%9},{%0,%1,%2,%3};"                    \
        : "+f"((d)[0]), "+f"((d)[1]), "+f"((d)[2]), "+f"((d)[3])                \
        : "r"((a)[0]), "r"((a)[1]), "r"((a)[2]), "r"((a)[3]), "r"(b0), "r"(b1))

// ---------------- A: transpose+split-convert, and direct fp16 copy (fused) ----------------
__global__ void k_stageA(const float* __restrict__ A0, const float* __restrict__ A1,
                         const float* __restrict__ A2) {
    __shared__ float t[32][33];
    int s = blockIdx.z;
    const float* A = (s == 0) ? A0 : ((s == 1) ? A1 : A2);
    int wb = blockIdx.x * 32, vb = blockIdx.y * 32;
#pragma unroll
    for (int j = 0; j < 32; j += 8) {
        float f = A[(size_t)(vb + threadIdx.y + j) * 1024 + wb + threadIdx.x];
        t[threadIdx.y + j][threadIdx.x] = f;
        g_Bh[((size_t)s << 20) + (size_t)(vb + threadIdx.y + j) * 1024 + wb + threadIdx.x] =
            __float2half(f);
    }
    __syncthreads();
#pragma unroll
    for (int j = 0; j < 32; j += 8) {
        float f = t[threadIdx.x][threadIdx.y + j];
        __half h = __float2half(f);
        size_t o = (size_t)(s * 2048 + wb + threadIdx.y + j) * 1024 + vb + threadIdx.x;
        g_Abf_h[o] = h;
        g_Abf_l[o] = __float2half(f - __half2float(h));
    }
}

// ---------------- x -> g_Xh[m'][v] and g_Xt[(b,v,l)][c]  (single pass) ----------------
__global__ __launch_bounds__(256) void k_stageX(const float* __restrict__ x) {
    __shared__ float sx[32][212];
    int b = blockIdx.y, v0 = blockIdx.x * 16;
    int tid = threadIdx.x;
    for (int e = tid; e < 32 * 52; e += 256) {
        int c = e / 52, q = e - c * 52;
        *(float4*)&sx[c][q * 4] =
            *(const float4*)(x + (size_t)(b * 32 + c) * MCOLS + v0 * 13 + q * 4);
    }
    __syncthreads();
    for (int e = tid; e < 208 * 4; e += 256) {
        int n = e >> 2, ch = e & 3;
        union { uint4 u; __half2 h[4]; } pk;
#pragma unroll
        for (int i = 0; i < 4; i++)
            pk.h[i] = __floats2half2_rn(sx[ch * 8 + 2 * i][n], sx[ch * 8 + 2 * i + 1][n]);
        *(uint4*)(g_Xt + ((size_t)b * MCOLS + v0 * 13 + n) * 32 + ch * 8) = pk.u;
    }
    for (int e = tid; e < 416 * 2; e += 256) {
        int r = e >> 1, vi0 = (e & 1) * 8;
        int l = r >> 5, c = r & 31;
        union { uint4 u; __half2 h[4]; } pk;
#pragma unroll
        for (int i = 0; i < 4; i++)
            pk.h[i] = __floats2half2_rn(sx[c][(vi0 + 2 * i) * 13 + l],
                                        sx[c][(vi0 + 2 * i + 1) * 13 + l]);
        *(uint4*)(g_Xh + (size_t)(b * 416 + r) * 1024 + v0 + vi0) = pk.u;
    }
}

__global__ void k_convW(const float* __restrict__ W) {
    int idx = blockIdx.x * 256 + threadIdx.x;
    if (idx >= 64 * CIN) return;
    g_Wh[idx] = __float2half(W[idx]);
}

// ---------------- gemm0: (A^T)^2 exact 2-term, BM=128 BN=128, 2-stage, 2 CTAs/SM ----------------
#define STAGE_B0 49152          // Ah 16K | Al 16K | X 16K
#define GEMM_DYN0 (2 * STAGE_B0)

__global__ __launch_bounds__(256, 2) void k_gemm0() {
    extern __shared__ char sm[];
    const uint32_t sbase = smem_u32(sm);
    const int tid = threadIdx.x, lane = tid & 31, wid = tid >> 5;

    int s = blockIdx.z;
    const __half* Ah = g_Abf_h + (size_t)(s * 2048) * 1024;
    const __half* Al = g_Abf_l + (size_t)(s * 2048) * 1024;
    const __half* Bh = g_Bh + ((size_t)s << 20);
    const size_t i0 = (size_t)blockIdx.x * 128;
    const size_t j0 = (size_t)blockIdx.y * 128;

    const int wm = (wid & 1) * 64;
    const int wn = (wid >> 1) * 32;
    const int arow = wm + (lane & 15);
    const int a_x7 = arow & 7;
    const int a_cs = lane >> 4;
    const int brow = wn + ((lane >> 4) << 3) + (lane & 7);
    const int b_x7 = brow & 7;
    const int b_cs = (lane >> 3) & 1;

    float acc[4][4][4];
#pragma unroll
    for (int mt = 0; mt < 4; mt++)
#pragma unroll
        for (int nt = 0; nt < 4; nt++)
#pragma unroll
            for (int q = 0; q < 4; q++) acc[mt][nt][q] = 0.f;

    auto load_stage = [&](int st, int buf) {
        const int kv0 = st * 64;
        const uint32_t sb = sbase + buf * STAGE_B0;
#pragma unroll
        for (int q = 0; q < 4; q++) {
            int id = tid + 256 * q;
            int row = id >> 3, kc = id & 7;
            uint32_t sw = row * 128 + ((kc ^ (row & 7)) << 4);
            size_t go = (i0 + row) * 1024 + kv0 + kc * 8;
            CP16(sb + sw, Ah + go);
            CP16(sb + 16384 + sw, Al + go);
            CP16(sb + 32768 + sw, Bh + (j0 + row) * 1024 + kv0 + kc * 8);
        }
    };

    load_stage(0, 0); CP_COMMIT();
    load_stage(1, 1); CP_COMMIT();

    for (int st = 0; st < 16; ++st) {
        CP_WAIT1();
        __syncthreads();
        const int buf = st & 1;
        const uint32_t sb = sbase + buf * STAGE_B0;
#pragma unroll
        for (int kk = 0; kk < 4; kk++) {
            uint32_t ah[4][4], al[4][4];
#pragma unroll
            for (int mt = 0; mt < 4; mt++) {
                uint32_t addr = sb + (arow + mt * 16) * 128 + (((kk * 2 + a_cs) ^ a_x7) << 4);
                LDSM4(ah[mt], addr);
                LDSM4(al[mt], addr + 16384);
            }
#pragma unroll
            for (int nt2 = 0; nt2 < 2; nt2++) {
                uint32_t bh[4];
                LDSM4(bh, sb + 32768 + (brow + nt2 * 16) * 128 +
                          (((kk * 2 + b_cs) ^ b_x7) << 4));
#pragma unroll
                for (int mt = 0; mt < 4; mt++) {
                    MMAH(acc[mt][nt2 * 2],     ah[mt], bh[0], bh[1]);
                    MMAH(acc[mt][nt2 * 2 + 1], ah[mt], bh[2], bh[3]);
                    MMAH(acc[mt][nt2 * 2],     al[mt], bh[0], bh[1]);
                    MMAH(acc[mt][nt2 * 2 + 1], al[mt], bh[2], bh[3]);
                }
            }
        }
        __syncthreads();
        if (st + 2 < 16) load_stage(st + 2, buf);
        CP_COMMIT();
    }

    // fp16 epilogue: rows s*2048 + 1024 + i of g_Abf_h (1-term operand for gemm1)
    const int crow = lane >> 2;
    const int ccol = (lane & 3) * 2;
    __half* C = g_Abf_h + (size_t)(s * 2048 + 1024) * 1024;
#pragma unroll
    for (int mt = 0; mt < 4; mt++) {
        size_t rbase = (i0 + wm + mt * 16 + crow) * 1024 + j0 + wn + ccol;
#pragma unroll
        for (int nt = 0; nt < 4; nt++) {
            __half* p = C + rbase + nt * 8;
            *(__half2*)p              = __floats2half2_rn(acc[mt][nt][0], acc[mt][nt][1]);
            *(__half2*)(p + 8 * 1024) = __floats2half2_rn(acc[mt][nt][2], acc[mt][nt][3]);
        }
    }
}

// ---------------- gemm1: diffusion 1-term, BM=256 BN=128 BK=64, 512 thr, 16 warps ----------------
#define STAGE_B1 49152          // A 32K | X 16K
#define GEMM_DYN1 (3 * STAGE_B1)

__global__ __launch_bounds__(512, 1) void k_gemm1() {
    extern __shared__ char sm[];
    const uint32_t sbase = smem_u32(sm);
    const int tid = threadIdx.x, lane = tid & 31, wid = tid >> 5;

    const size_t i0 = (size_t)blockIdx.x * 256;
    const size_t j0 = (size_t)blockIdx.y * 128;

    const int wm = (wid & 3) * 64;
    const int wn = (wid >> 2) * 32;
    const int arow = wm + (lane & 15);
    const int a_x7 = arow & 7;
    const int a_cs = lane >> 4;
    const int brow = wn + ((lane >> 4) << 3) + (lane & 7);
    const int b_x7 = brow & 7;
    const int b_cs = (lane >> 3) & 1;

    float acc[4][4][4];
#pragma unroll
    for (int mt = 0; mt < 4; mt++)
#pragma unroll
        for (int nt = 0; nt < 4; nt++)
#pragma unroll
            for (int q = 0; q < 4; q++) acc[mt][nt][q] = 0.f;

    auto load_stage = [&](int st, int buf) {
        const int kv0 = st * 64;
        const uint32_t sb = sbase + buf * STAGE_B1;
        // A: 256 rows x 8 chunks = 2048 cp16
#pragma unroll
        for (int q = 0; q < 4; q++) {
            int id = tid + 512 * q;
            int row = id >> 3, kc = id & 7;
            uint32_t sw = row * 128 + ((kc ^ (row & 7)) << 4);
            CP16(sb + sw, g_Abf_h + (i0 + row) * 1024 + kv0 + kc * 8);
        }
        // X: 128 rows x 8 chunks = 1024 cp16
#pragma unroll
        for (int q = 0; q < 2; q++) {
            int id = tid + 512 * q;
            int row = id >> 3, kc = id & 7;
            uint32_t sw = row * 128 + ((kc ^ (row & 7)) << 4);
            CP16(sb + 32768 + sw, g_Xh + (j0 + row) * 1024 + kv0 + kc * 8);
        }
    };

    load_stage(0, 0); CP_COMMIT();
    load_stage(1, 1); CP_COMMIT();
    load_stage(2, 2); CP_COMMIT();

    int buf = 0;
    for (int st = 0; st < 16; ++st) {
        CP_WAIT2();
        __syncthreads();
        const uint32_t sb = sbase + buf * STAGE_B1;
#pragma unroll
        for (int kk = 0; kk < 4; kk++) {
            uint32_t ah[4][4];
#pragma unroll
            for (int mt = 0; mt < 4; mt++)
                LDSM4(ah[mt], sb + (arow + mt * 16) * 128 + (((kk * 2 + a_cs) ^ a_x7) << 4));
#pragma unroll
            for (int nt2 = 0; nt2 < 2; nt2++) {
                uint32_t bh[4];
                LDSM4(bh, sb + 32768 + (brow + nt2 * 16) * 128 +
                          (((kk * 2 + b_cs) ^ b_x7) << 4));
#pragma unroll
                for (int mt = 0; mt < 4; mt++) {
                    MMAH(acc[mt][nt2 * 2],     ah[mt], bh[0], bh[1]);
                    MMAH(acc[mt][nt2 * 2 + 1], ah[mt], bh[2], bh[3]);
                }
            }
        }
        __syncthreads();
        if (st + 3 < 16) load_stage(st + 3, buf);
        CP_COMMIT();
        buf = (buf + 1 == 3) ? 0 : buf + 1;
    }

    const int crow = lane >> 2;
    const int ccol = (lane & 3) * 2;
#pragma unroll
    for (int mt = 0; mt < 4; mt++) {
        size_t rbase = (i0 + wm + mt * 16 + crow) * MCOLS + j0 + wn + ccol;
#pragma unroll
        for (int nt = 0; nt < 4; nt++) {
            __half* p = g_yt + rbase + nt * 8;
            *(__half2*)p               = __floats2half2_rn(acc[mt][nt][0], acc[mt][nt][1]);
            *(__half2*)(p + 8 * MCOLS) = __floats2half2_rn(acc[mt][nt][2], acc[mt][nt][3]);
        }
    }
}

// ---------------- final MMA: out = Wh * H + bias; H gathered from g_Xt + g_yt ----------------
#define FIN_W    0
#define FIN_HS   (64 * PAD_E * 2)               // 29696
#define FIN_DYN  (FIN_HS + 128 * PAD_E * 2)     // 89088

__global__ __launch_bounds__(256, 2) void k_final(const float* __restrict__ bias,
                                                  float* __restrict__ out) {
    extern __shared__ char sm[];
    const uint32_t sbase = smem_u32(sm);
    const int tid = threadIdx.x, lane = tid & 31, wid = tid >> 5;
    const int b = blockIdx.y;
    const int j0 = blockIdx.x * 128;

    for (int e = tid; e < 64 * 28; e += 256) {
        int r = e / 28, q = e - r * 28;
        CP16(sbase + FIN_W + r * 464 + q * 16, g_Wh + r * CIN + q * 8);
    }
    for (int e = tid; e < 128 * 14; e += 256) {
        int r = e / 14, q = e - r * 14;
        int n = j0 + r;
        int v = n / 13, l = n - v * 13;
        const __half* src;
        if (q < 4)
            src = g_Xt + ((size_t)b * MCOLS + n) * 32 + q * 8;
        else {
            int g = (q - 4) >> 2, ch = (q - 4) & 3;
            src = g_yt + ((size_t)(g * 1024 + v)) * MCOLS + b * 416 + l * 32 + ch * 8;
        }
        CP16(sbase + FIN_HS + r * 464 + q * 16, src);
    }
    CP_COMMIT();
    for (int e = tid; e < 128 * 14; e += 256) {
        int r = e / 14, q = 14 + (e - r * 14);
        int n = j0 + r;
        int v = n / 13, l = n - v * 13;
        int g = (q - 4) >> 2, ch = (q - 4) & 3;
        const __half* src = g_yt + ((size_t)(g * 1024 + v)) * MCOLS + b * 416 + l * 32 + ch * 8;
        CP16(sbase + FIN_HS + r * 464 + q * 16, src);
    }
    CP_COMMIT();

    const int wm = (wid & 1) * 32;
    const int wn = (wid >> 1) * 32;
    const int arow_l = lane & 15;
    const int a_cs = lane >> 4;
    const int brow_l = ((lane >> 4) << 3) + (lane & 7);
    const int b_cs = (lane >> 3) & 1;

    float acc[2][4][4];
#pragma unroll
    for (int mt = 0; mt < 2; mt++)
#pragma unroll
        for (int nt = 0; nt < 4; nt++)
#pragma unroll
            for (int q = 0; q < 4; q++) acc[mt][nt][q] = 0.f;

    CP_WAIT1();
    __syncthreads();

#pragma unroll
    for (int kc = 0; kc < 7; kc++) {
        uint32_t wh[2][4];
#pragma unroll
        for (int mt = 0; mt < 2; mt++)
            LDSM4(wh[mt], sbase + FIN_W + (wm + mt * 16 + arow_l) * 464 + (kc * 2 + a_cs) * 16);
#pragma unroll
        for (int nt2 = 0; nt2 < 2; nt2++) {
            uint32_t bh[4];
            LDSM4(bh, sbase + FIN_HS + (wn + nt2 * 16 + brow_l) * 464 +
                      (kc * 2 + b_cs) * 16);
#pragma unroll
            for (int mt = 0; mt < 2; mt++) {
                MMAH(acc[mt][nt2 * 2],     wh[mt], bh[0], bh[1]);
                MMAH(acc[mt][nt2 * 2 + 1], wh[mt], bh[2], bh[3]);
            }
        }
    }

    CP_WAIT0();
    __syncthreads();

#pragma unroll
    for (int kc = 7; kc < 14; kc++) {
        uint32_t wh[2][4];
#pragma unroll
        for (int mt = 0; mt < 2; mt++)
            LDSM4(wh[mt], sbase + FIN_W + (wm + mt * 16 + arow_l) * 464 + (kc * 2 + a_cs) * 16);
#pragma unroll
        for (int nt2 = 0; nt2 < 2; nt2++) {
            uint32_t bh[4];
            LDSM4(bh, sbase + FIN_HS + (wn + nt2 * 16 + brow_l) * 464 +
                      (kc * 2 + b_cs) * 16);
#pragma unroll
            for (int mt = 0; mt < 2; mt++) {
                MMAH(acc[mt][nt2 * 2],     wh[mt], bh[0], bh[1]);
                MMAH(acc[mt][nt2 * 2 + 1], wh[mt], bh[2], bh[3]);
            }
        }
    }

    const int crow = lane >> 2;
    const int ccol = (lane & 3) * 2;
#pragma unroll
    for (int mt = 0; mt < 2; mt++) {
        int o = wm + mt * 16 + crow;
        float b0 = bias[o], b1 = bias[o + 8];
        size_t r0 = (size_t)(b * 64 + o) * MCOLS + j0 + wn + ccol;
#pragma unroll
        for (int nt = 0; nt < 4; nt++) {
            float* p = out + r0 + nt * 8;
            *(float2*)p               = make_float2(acc[mt][nt][0] + b0, acc[mt][nt][1] + b0);
            *(float2*)(p + 8 * MCOLS) = make_float2(acc[mt][nt][2] + b1, acc[mt][nt][3] + b1);
        }
    }
}

// ---------------- launcher ----------------
extern "C" void kernel_launch(void* const* d_in, const int* in_sizes, int n_in,
                              void* d_out, int out_size) {
    const float* x    = (const float*)d_in[0];
    const float* A0   = (const float*)d_in[1];
    const float* A1   = (const float*)d_in[2];
    const float* A2   = (const float*)d_in[3];
    const float* W    = (const float*)d_in[4];
    const float* bias = (const float*)d_in[5];
    float* out = (float*)d_out;

    cudaFuncSetAttribute(k_gemm0, cudaFuncAttributeMaxDynamicSharedMemorySize, GEMM_DYN0);
    cudaFuncSetAttribute(k_gemm1, cudaFuncAttributeMaxDynamicSharedMemorySize, GEMM_DYN1);
    cudaFuncSetAttribute(k_final, cudaFuncAttributeMaxDynamicSharedMemorySize, FIN_DYN);

    k_stageA<<<dim3(32, 32, 3), dim3(32, 8)>>>(A0, A1, A2);
    k_stageX<<<dim3(64, 32), 256>>>(x);
    k_convW<<<56, 256>>>(W);

    k_gemm0<<<dim3(8, 8, 3), 256, GEMM_DYN0>>>();   // (A^T)^2 -> fp16 rows of g_Abf_h

    k_gemm1<<<dim3(24, 104), 512, GEMM_DYN1>>>();   // diffusion -> g_yt

    k_final<<<dim3(104, 32), 256, FIN_DYN>>>(bias, out);
}

// round 13
// speedup vs baseline: 1.1440x; 1.1440x over previous
#include <cuda_runtime.h>
#include <cuda_fp16.h>
#include <cstdint>

// GraphConvNet: B=32, C=32, V=1024, L=13, support=3, order=2
// R11 kernels + graph fork-join: gemm0 overlapped with stageX + gemm1(first-order half).

#define V_N   1024
#define MCOLS 13312
#define MI    6144
#define CIN   224
#define NB    32
#define PAD_E 232

// ---------------- scratch ----------------
__device__ __align__(16) __half g_yt [(size_t)MI * MCOLS];      // [i=(g,v)][m'=(b,l,c)]
__device__ __align__(16) __half g_Abf_h[(size_t)MI * V_N];
__device__ __align__(16) __half g_Abf_l[(size_t)MI * V_N];
__device__ __align__(16) __half g_Bh [3u * 1024u * 1024u];
__device__ __align__(16) __half g_Xh [(size_t)MCOLS * V_N];     // [m'=(b,l,c)][v]
__device__ __align__(16) __half g_Xt [(size_t)NB * MCOLS * 32]; // [(b,v,l)][c]
__device__ __align__(16) __half g_Wh [64 * CIN];

// ================= helpers =================
__device__ __forceinline__ uint32_t smem_u32(const void* p) {
    uint32_t a;
    asm("{ .reg .u64 t; cvta.to.shared.u64 t, %1; cvt.u32.u64 %0, t; }" : "=r"(a) : "l"(p));
    return a;
}
#define CP16(s, g) asm volatile("cp.async.cg.shared.global [%0], [%1], 16;" :: "r"(s), "l"(g))
#define CP_COMMIT() asm volatile("cp.async.commit_group;")
#define CP_WAIT2()  asm volatile("cp.async.wait_group 2;")
#define CP_WAIT1()  asm volatile("cp.async.wait_group 1;")
#define CP_WAIT0()  asm volatile("cp.async.wait_group 0;")

#define LDSM4(r, addr)                                                          \
    asm volatile("ldmatrix.sync.aligned.m8n8.x4.shared.b16 {%0,%1,%2,%3}, [%4];"\
        : "=r"((r)[0]), "=r"((r)[1]), "=r"((r)[2]), "=r"((r)[3]) : "r"(addr))

#define MMAH(d, a, b0, b1)                                                      \
    asm volatile("mma.sync.aligned.m16n8k16.row.col.f32.f16.f16.f32 "           \
        "{%0,%1,%2,%3},{%4,%5,%6,%7},{%8,%9},{%0,%1,%2,%3};"                    \
        : "+f"((d)[0]), "+f"((d)[1]), "+f"((d)[2]), "+f"((d)[3])                \
        : "r"((a)[0]), "r"((a)[1]), "r"((a)[2]), "r"((a)[3]), "r"(b0), "r"(b1))

// ---------------- A: transpose+split-convert + direct fp16 copy ----------------
__global__ void k_stageA(const float* __restrict__ A0, const float* __restrict__ A1,
                         const float* __restrict__ A2) {
    __shared__ float t[32][33];
    int s = blockIdx.z;
    const float* A = (s == 0) ? A0 : ((s == 1) ? A1 : A2);
    int wb = blockIdx.x * 32, vb = blockIdx.y * 32;
#pragma unroll
    for (int j = 0; j < 32; j += 8) {
        float f = A[(size_t)(vb + threadIdx.y + j) * 1024 + wb + threadIdx.x];
        t[threadIdx.y + j][threadIdx.x] = f;
        g_Bh[((size_t)s << 20) + (size_t)(vb + threadIdx.y + j) * 1024 + wb + threadIdx.x] =
            __float2half(f);
    }
    __syncthreads();
#pragma unroll
    for (int j = 0; j < 32; j += 8) {
        float f = t[threadIdx.x][threadIdx.y + j];
        __half h = __float2half(f);
        size_t o = (size_t)(s * 2048 + wb + threadIdx.y + j) * 1024 + vb + threadIdx.x;
        g_Abf_h[o] = h;
        g_Abf_l[o] = __float2half(f - __half2float(h));
    }
}

// ---------------- x -> g_Xh[m'][v] and g_Xt[(b,v,l)][c] ----------------
__global__ __launch_bounds__(256) void k_stageX(const float* __restrict__ x) {
    __shared__ float sx[32][212];
    int b = blockIdx.y, v0 = blockIdx.x * 16;
    int tid = threadIdx.x;
    for (int e = tid; e < 32 * 52; e += 256) {
        int c = e / 52, q = e - c * 52;
        *(float4*)&sx[c][q * 4] =
            *(const float4*)(x + (size_t)(b * 32 + c) * MCOLS + v0 * 13 + q * 4);
    }
    __syncthreads();
    for (int e = tid; e < 208 * 4; e += 256) {
        int n = e >> 2, ch = e & 3;
        union { uint4 u; __half2 h[4]; } pk;
#pragma unroll
        for (int i = 0; i < 4; i++)
            pk.h[i] = __floats2half2_rn(sx[ch * 8 + 2 * i][n], sx[ch * 8 + 2 * i + 1][n]);
        *(uint4*)(g_Xt + ((size_t)b * MCOLS + v0 * 13 + n) * 32 + ch * 8) = pk.u;
    }
    for (int e = tid; e < 416 * 2; e += 256) {
        int r = e >> 1, vi0 = (e & 1) * 8;
        int l = r >> 5, c = r & 31;
        union { uint4 u; __half2 h[4]; } pk;
#pragma unroll
        for (int i = 0; i < 4; i++)
            pk.h[i] = __floats2half2_rn(sx[c][(vi0 + 2 * i) * 13 + l],
                                        sx[c][(vi0 + 2 * i + 1) * 13 + l]);
        *(uint4*)(g_Xh + (size_t)(b * 416 + r) * 1024 + v0 + vi0) = pk.u;
    }
}

__global__ void k_convW(const float* __restrict__ W) {
    int idx = blockIdx.x * 256 + threadIdx.x;
    if (idx >= 64 * CIN) return;
    g_Wh[idx] = __float2half(W[idx]);
}

// ---------------- gemm0: (A^T)^2 exact 2-term, BM=128 BN=256, 3-stage (R11 shape) ----------------
#define STAGE_B0 65536
#define GEMM_DYN0 (3 * STAGE_B0)

__global__ __launch_bounds__(256, 1) void k_gemm0() {
    extern __shared__ char sm[];
    const uint32_t sbase = smem_u32(sm);
    const int tid = threadIdx.x, lane = tid & 31, wid = tid >> 5;

    int s = blockIdx.z;
    const __half* Ah = g_Abf_h + (size_t)(s * 2048) * 1024;
    const __half* Al = g_Abf_l + (size_t)(s * 2048) * 1024;
    const __half* Bh = g_Bh + ((size_t)s << 20);
    const size_t i0 = (size_t)blockIdx.x * 128;
    const size_t j0 = (size_t)blockIdx.y * 256;

    const int wm = (wid & 1) * 64;
    const int wn = (wid >> 1) * 64;
    const int arow = wm + (lane & 15);
    const int a_x7 = arow & 7;
    const int a_cs = lane >> 4;
    const int brow = wn + ((lane >> 4) << 3) + (lane & 7);
    const int b_x7 = brow & 7;
    const int b_cs = (lane >> 3) & 1;

    float acc[4][8][4];
#pragma unroll
    for (int mt = 0; mt < 4; mt++)
#pragma unroll
        for (int nt = 0; nt < 8; nt++)
#pragma unroll
            for (int q = 0; q < 4; q++) acc[mt][nt][q] = 0.f;

    auto load_stage = [&](int st, int buf) {
        const int kv0 = st * 64;
        const uint32_t sb = sbase + buf * STAGE_B0;
#pragma unroll
        for (int q = 0; q < 4; q++) {
            int id = tid + 256 * q;
            int row = id >> 3, kc = id & 7;
            uint32_t sw = row * 128 + ((kc ^ (row & 7)) << 4);
            size_t go = (i0 + row) * 1024 + kv0 + kc * 8;
            CP16(sb + sw, Ah + go);
            CP16(sb + 16384 + sw, Al + go);
        }
#pragma unroll
        for (int q = 0; q < 8; q++) {
            int id = tid + 256 * q;
            int row = id >> 3, kc = id & 7;
            uint32_t sw = row * 128 + ((kc ^ (row & 7)) << 4);
            CP16(sb + 32768 + sw, Bh + (j0 + row) * 1024 + kv0 + kc * 8);
        }
    };

    load_stage(0, 0); CP_COMMIT();
    load_stage(1, 1); CP_COMMIT();
    load_stage(2, 2); CP_COMMIT();

    int buf = 0;
    for (int st = 0; st < 16; ++st) {
        CP_WAIT2();
        __syncthreads();
        const uint32_t sb = sbase + buf * STAGE_B0;
#pragma unroll
        for (int kk = 0; kk < 4; kk++) {
            uint32_t ah[4][4], al[4][4];
#pragma unroll
            for (int mt = 0; mt < 4; mt++) {
                uint32_t addr = sb + (arow + mt * 16) * 128 + (((kk * 2 + a_cs) ^ a_x7) << 4);
                LDSM4(ah[mt], addr);
                LDSM4(al[mt], addr + 16384);
            }
#pragma unroll
            for (int nt2 = 0; nt2 < 4; nt2++) {
                uint32_t bh[4];
                LDSM4(bh, sb + 32768 + (brow + nt2 * 16) * 128 +
                          (((kk * 2 + b_cs) ^ b_x7) << 4));
#pragma unroll
                for (int mt = 0; mt < 4; mt++) {
                    MMAH(acc[mt][nt2 * 2],     ah[mt], bh[0], bh[1]);
                    MMAH(acc[mt][nt2 * 2 + 1], ah[mt], bh[2], bh[3]);
                    MMAH(acc[mt][nt2 * 2],     al[mt], bh[0], bh[1]);
                    MMAH(acc[mt][nt2 * 2 + 1], al[mt], bh[2], bh[3]);
                }
            }
        }
        __syncthreads();
        if (st + 3 < 16) load_stage(st + 3, buf);
        CP_COMMIT();
        buf = (buf + 1 == 3) ? 0 : buf + 1;
    }

    const int crow = lane >> 2;
    const int ccol = (lane & 3) * 2;
    __half* C = g_Abf_h + (size_t)(s * 2048 + 1024) * 1024;
#pragma unroll
    for (int mt = 0; mt < 4; mt++) {
        size_t rbase = (i0 + wm + mt * 16 + crow) * 1024 + j0 + wn + ccol;
#pragma unroll
        for (int nt = 0; nt < 8; nt++) {
            __half* p = C + rbase + nt * 8;
            *(__half2*)p              = __floats2half2_rn(acc[mt][nt][0], acc[mt][nt][1]);
            *(__half2*)(p + 8 * 1024) = __floats2half2_rn(acc[mt][nt][2], acc[mt][nt][3]);
        }
    }
}

// ---------------- gemm1: diffusion 1-term, BM=128 BN=128, 2 CTAs/SM (R11 shape) ----------------
// half = 0: first-order i-tiles (rows s*2048 + [0,1024)); half = 1: squared rows.
#define STAGE_B1 32768
#define GEMM_DYN1 (3 * STAGE_B1)

__global__ __launch_bounds__(256, 2) void k_gemm1(int half) {
    extern __shared__ char sm[];
    const uint32_t sbase = smem_u32(sm);
    const int tid = threadIdx.x, lane = tid & 31, wid = tid >> 5;

    const size_t i0 = (size_t)(((blockIdx.x >> 3) * 16) + half * 8 + (blockIdx.x & 7)) * 128;
    const size_t j0 = (size_t)blockIdx.y * 128;

    const int wm = (wid & 1) * 64;
    const int wn = (wid >> 1) * 32;
    const int arow = wm + (lane & 15);
    const int a_x7 = arow & 7;
    const int a_cs = lane >> 4;
    const int brow = wn + ((lane >> 4) << 3) + (lane & 7);
    const int b_x7 = brow & 7;
    const int b_cs = (lane >> 3) & 1;

    float acc[4][4][4];
#pragma unroll
    for (int mt = 0; mt < 4; mt++)
#pragma unroll
        for (int nt = 0; nt < 4; nt++)
#pragma unroll
            for (int q = 0; q < 4; q++) acc[mt][nt][q] = 0.f;

    auto load_stage = [&](int st, int buf) {
        const int kv0 = st * 64;
        const uint32_t sb = sbase + buf * STAGE_B1;
#pragma unroll
        for (int q = 0; q < 4; q++) {
            int id = tid + 256 * q;
            int row = id >> 3, kc = id & 7;
            uint32_t sw = row * 128 + ((kc ^ (row & 7)) << 4);
            CP16(sb + sw, g_Abf_h + (i0 + row) * 1024 + kv0 + kc * 8);
        }
#pragma unroll
        for (int q = 0; q < 4; q++) {
            int id = tid + 256 * q;
            int row = id >> 3, kc = id & 7;
            uint32_t sw = row * 128 + ((kc ^ (row & 7)) << 4);
            CP16(sb + 16384 + sw, g_Xh + (j0 + row) * 1024 + kv0 + kc * 8);
        }
    };

    load_stage(0, 0); CP_COMMIT();
    load_stage(1, 1); CP_COMMIT();
    load_stage(2, 2); CP_COMMIT();

    int buf = 0;
    for (int st = 0; st < 16; ++st) {
        CP_WAIT2();
        __syncthreads();
        const uint32_t sb = sbase + buf * STAGE_B1;
#pragma unroll
        for (int kk = 0; kk < 4; kk++) {
            uint32_t ah[4][4];
#pragma unroll
            for (int mt = 0; mt < 4; mt++)
                LDSM4(ah[mt], sb + (arow + mt * 16) * 128 + (((kk * 2 + a_cs) ^ a_x7) << 4));
#pragma unroll
            for (int nt2 = 0; nt2 < 2; nt2++) {
                uint32_t bh[4];
                LDSM4(bh, sb + 16384 + (brow + nt2 * 16) * 128 +
                          (((kk * 2 + b_cs) ^ b_x7) << 4));
#pragma unroll
                for (int mt = 0; mt < 4; mt++) {
                    MMAH(acc[mt][nt2 * 2],     ah[mt], bh[0], bh[1]);
                    MMAH(acc[mt][nt2 * 2 + 1], ah[mt], bh[2], bh[3]);
                }
            }
        }
        __syncthreads();
        if (st + 3 < 16) load_stage(st + 3, buf);
        CP_COMMIT();
        buf = (buf + 1 == 3) ? 0 : buf + 1;
    }

    const int crow = lane >> 2;
    const int ccol = (lane & 3) * 2;
#pragma unroll
    for (int mt = 0; mt < 4; mt++) {
        size_t rbase = (i0 + wm + mt * 16 + crow) * MCOLS + j0 + wn + ccol;
#pragma unroll
        for (int nt = 0; nt < 4; nt++) {
            __half* p = g_yt + rbase + nt * 8;
            *(__half2*)p               = __floats2half2_rn(acc[mt][nt][0], acc[mt][nt][1]);
            *(__half2*)(p + 8 * MCOLS) = __floats2half2_rn(acc[mt][nt][2], acc[mt][nt][3]);
        }
    }
}

// ---------------- final MMA: out = Wh * H + bias (pipelined staging) ----------------
#define FIN_W    0
#define FIN_HS   (64 * PAD_E * 2)
#define FIN_DYN  (FIN_HS + 128 * PAD_E * 2)

__global__ __launch_bounds__(256, 2) void k_final(const float* __restrict__ bias,
                                                  float* __restrict__ out) {
    extern __shared__ char sm[];
    const uint32_t sbase = smem_u32(sm);
    const int tid = threadIdx.x, lane = tid & 31, wid = tid >> 5;
    const int b = blockIdx.y;
    const int j0 = blockIdx.x * 128;

    for (int e = tid; e < 64 * 28; e += 256) {
        int r = e / 28, q = e - r * 28;
        CP16(sbase + FIN_W + r * 464 + q * 16, g_Wh + r * CIN + q * 8);
    }
    for (int e = tid; e < 128 * 14; e += 256) {
        int r = e / 14, q = e - r * 14;
        int n = j0 + r;
        int v = n / 13, l = n - v * 13;
        const __half* src;
        if (q < 4)
            src = g_Xt + ((size_t)b * MCOLS + n) * 32 + q * 8;
        else {
            int g = (q - 4) >> 2, ch = (q - 4) & 3;
            src = g_yt + ((size_t)(g * 1024 + v)) * MCOLS + b * 416 + l * 32 + ch * 8;
        }
        CP16(sbase + FIN_HS + r * 464 + q * 16, src);
    }
    CP_COMMIT();
    for (int e = tid; e < 128 * 14; e += 256) {
        int r = e / 14, q = 14 + (e - r * 14);
        int n = j0 + r;
        int v = n / 13, l = n - v * 13;
        int g = (q - 4) >> 2, ch = (q - 4) & 3;
        const __half* src = g_yt + ((size_t)(g * 1024 + v)) * MCOLS + b * 416 + l * 32 + ch * 8;
        CP16(sbase + FIN_HS + r * 464 + q * 16, src);
    }
    CP_COMMIT();

    const int wm = (wid & 1) * 32;
    const int wn = (wid >> 1) * 32;
    const int arow_l = lane & 15;
    const int a_cs = lane >> 4;
    const int brow_l = ((lane >> 4) << 3) + (lane & 7);
    const int b_cs = (lane >> 3) & 1;

    float acc[2][4][4];
#pragma unroll
    for (int mt = 0; mt < 2; mt++)
#pragma unroll
        for (int nt = 0; nt < 4; nt++)
#pragma unroll
            for (int q = 0; q < 4; q++) acc[mt][nt][q] = 0.f;

    CP_WAIT1();
    __syncthreads();

#pragma unroll
    for (int kc = 0; kc < 7; kc++) {
        uint32_t wh[2][4];
#pragma unroll
        for (int mt = 0; mt < 2; mt++)
            LDSM4(wh[mt], sbase + FIN_W + (wm + mt * 16 + arow_l) * 464 + (kc * 2 + a_cs) * 16);
#pragma unroll
        for (int nt2 = 0; nt2 < 2; nt2++) {
            uint32_t bh[4];
            LDSM4(bh, sbase + FIN_HS + (wn + nt2 * 16 + brow_l) * 464 +
                      (kc * 2 + b_cs) * 16);
#pragma unroll
            for (int mt = 0; mt < 2; mt++) {
                MMAH(acc[mt][nt2 * 2],     wh[mt], bh[0], bh[1]);
                MMAH(acc[mt][nt2 * 2 + 1], wh[mt], bh[2], bh[3]);
            }
        }
    }

    CP_WAIT0();
    __syncthreads();

#pragma unroll
    for (int kc = 7; kc < 14; kc++) {
        uint32_t wh[2][4];
#pragma unroll
        for (int mt = 0; mt < 2; mt++)
            LDSM4(wh[mt], sbase + FIN_W + (wm + mt * 16 + arow_l) * 464 + (kc * 2 + a_cs) * 16);
#pragma unroll
        for (int nt2 = 0; nt2 < 2; nt2++) {
            uint32_t bh[4];
            LDSM4(bh, sbase + FIN_HS + (wn + nt2 * 16 + brow_l) * 464 +
                      (kc * 2 + b_cs) * 16);
#pragma unroll
            for (int mt = 0; mt < 2; mt++) {
                MMAH(acc[mt][nt2 * 2],     wh[mt], bh[0], bh[1]);
                MMAH(acc[mt][nt2 * 2 + 1], wh[mt], bh[2], bh[3]);
            }
        }
    }

    const int crow = lane >> 2;
    const int ccol = (lane & 3) * 2;
#pragma unroll
    for (int mt = 0; mt < 2; mt++) {
        int o = wm + mt * 16 + crow;
        float b0 = bias[o], b1 = bias[o + 8];
        size_t r0 = (size_t)(b * 64 + o) * MCOLS + j0 + wn + ccol;
#pragma unroll
        for (int nt = 0; nt < 4; nt++) {
            float* p = out + r0 + nt * 8;
            *(float2*)p               = make_float2(acc[mt][nt][0] + b0, acc[mt][nt][1] + b0);
            *(float2*)(p + 8 * MCOLS) = make_float2(acc[mt][nt][2] + b1, acc[mt][nt][3] + b1);
        }
    }
}

// ---------------- launcher: fork-join overlap ----------------
extern "C" void kernel_launch(void* const* d_in, const int* in_sizes, int n_in,
                              void* d_out, int out_size) {
    const float* x    = (const float*)d_in[0];
    const float* A0   = (const float*)d_in[1];
    const float* A1   = (const float*)d_in[2];
    const float* A2   = (const float*)d_in[3];
    const float* W    = (const float*)d_in[4];
    const float* bias = (const float*)d_in[5];
    float* out = (float*)d_out;

    static cudaStream_t s2 = nullptr;
    static cudaEvent_t e0 = nullptr, eA = nullptr, eJ = nullptr;
    if (!s2) {
        cudaStreamCreateWithFlags(&s2, cudaStreamNonBlocking);
        cudaEventCreateWithFlags(&e0, cudaEventDisableTiming);
        cudaEventCreateWithFlags(&eA, cudaEventDisableTiming);
        cudaEventCreateWithFlags(&eJ, cudaEventDisableTiming);
        cudaFuncSetAttribute(k_gemm0, cudaFuncAttributeMaxDynamicSharedMemorySize, GEMM_DYN0);
        cudaFuncSetAttribute(k_gemm1, cudaFuncAttributeMaxDynamicSharedMemorySize, GEMM_DYN1);
        cudaFuncSetAttribute(k_final, cudaFuncAttributeMaxDynamicSharedMemorySize, FIN_DYN);
    }

    // fork: side stream joins the capture
    cudaEventRecord(e0, 0);
    cudaStreamWaitEvent(s2, e0, 0);

    // side stream: stageX, convW (independent of A)
    k_stageX<<<dim3(64, 32), 256, 0, s2>>>(x);
    k_convW<<<56, 256, 0, s2>>>(W);

    // main stream: stageA, then gemm0
    k_stageA<<<dim3(32, 32, 3), dim3(32, 8)>>>(A0, A1, A2);
    cudaEventRecord(eA, 0);
    k_gemm0<<<dim3(8, 4, 3), 256, GEMM_DYN0>>>();

    // side stream: first-order diffusion tiles (need stageA + stageX, NOT gemm0)
    cudaStreamWaitEvent(s2, eA, 0);
    k_gemm1<<<dim3(24, 104), 256, GEMM_DYN1, s2>>>(0);
    cudaEventRecord(eJ, s2);

    // join, then squared-row diffusion tiles (need gemm0 + stageX)
    cudaStreamWaitEvent(0, eJ, 0);
    k_gemm1<<<dim3(24, 104), 256, GEMM_DYN1>>>(1);

    k_final<<<dim3(104, 32), 256, FIN_DYN>>>(bias, out);
}

// round 14
// speedup vs baseline: 1.1527x; 1.0076x over previous
#include <cuda_runtime.h>
#include <cuda_fp16.h>
#include <cstdint>

// GraphConvNet: B=32, C=32, V=1024, L=13, support=3, order=2
// R13 fork-join + 96KB gemm0 (2-stage) so gemm0 co-resides with gemm1a on the same SMs.

#define V_N   1024
#define MCOLS 13312
#define MI    6144
#define CIN   224
#define NB    32
#define PAD_E 232

// ---------------- scratch ----------------
__device__ __align__(16) __half g_yt [(size_t)MI * MCOLS];      // [i=(g,v)][m'=(b,l,c)]
__device__ __align__(16) __half g_Abf_h[(size_t)MI * V_N];
__device__ __align__(16) __half g_Abf_l[(size_t)MI * V_N];
__device__ __align__(16) __half g_Bh [3u * 1024u * 1024u];
__device__ __align__(16) __half g_Xh [(size_t)MCOLS * V_N];     // [m'=(b,l,c)][v]
__device__ __align__(16) __half g_Xt [(size_t)NB * MCOLS * 32]; // [(b,v,l)][c]
__device__ __align__(16) __half g_Wh [64 * CIN];

// ================= helpers =================
__device__ __forceinline__ uint32_t smem_u32(const void* p) {
    uint32_t a;
    asm("{ .reg .u64 t; cvta.to.shared.u64 t, %1; cvt.u32.u64 %0, t; }" : "=r"(a) : "l"(p));
    return a;
}
#define CP16(s, g) asm volatile("cp.async.cg.shared.global [%0], [%1], 16;" :: "r"(s), "l"(g))
#define CP_COMMIT() asm volatile("cp.async.commit_group;")
#define CP_WAIT2()  asm volatile("cp.async.wait_group 2;")
#define CP_WAIT1()  asm volatile("cp.async.wait_group 1;")
#define CP_WAIT0()  asm volatile("cp.async.wait_group 0;")

#define LDSM4(r, addr)                                                          \
    asm volatile("ldmatrix.sync.aligned.m8n8.x4.shared.b16 {%0,%1,%2,%3}, [%4];"\
        : "=r"((r)[0]), "=r"((r)[1]), "=r"((r)[2]), "=r"((r)[3]) : "r"(addr))

#define MMAH(d, a, b0, b1)                                                      \
    asm volatile("mma.sync.aligned.m16n8k16.row.col.f32.f16.f16.f32 "           \
        "{%0,%1,%2,%3},{%4,%5,%6,%7},{%8,%9},{%0,%1,%2,%3};"                    \
        : "+f"((d)[0]), "+f"((d)[1]), "+f"((d)[2]), "+f"((d)[3])                \
        : "r"((a)[0]), "r"((a)[1]), "r"((a)[2]), "r"((a)[3]), "r"(b0), "r"(b1))

// ---------------- A: transpose+split-convert + direct fp16 copy ----------------
__global__ void k_stageA(const float* __restrict__ A0, const float* __restrict__ A1,
                         const float* __restrict__ A2) {
    __shared__ float t[32][33];
    int s = blockIdx.z;
    const float* A = (s == 0) ? A0 : ((s == 1) ? A1 : A2);
    int wb = blockIdx.x * 32, vb = blockIdx.y * 32;
#pragma unroll
    for (int j = 0; j < 32; j += 8) {
        float f = A[(size_t)(vb + threadIdx.y + j) * 1024 + wb + threadIdx.x];
        t[threadIdx.y + j][threadIdx.x] = f;
        g_Bh[((size_t)s << 20) + (size_t)(vb + threadIdx.y + j) * 1024 + wb + threadIdx.x] =
            __float2half(f);
    }
    __syncthreads();
#pragma unroll
    for (int j = 0; j < 32; j += 8) {
        float f = t[threadIdx.x][threadIdx.y + j];
        __half h = __float2half(f);
        size_t o = (size_t)(s * 2048 + wb + threadIdx.y + j) * 1024 + vb + threadIdx.x;
        g_Abf_h[o] = h;
        g_Abf_l[o] = __float2half(f - __half2float(h));
    }
}

// ---------------- x -> g_Xh[m'][v] and g_Xt[(b,v,l)][c] ----------------
__global__ __launch_bounds__(256) void k_stageX(const float* __restrict__ x) {
    __shared__ float sx[32][212];
    int b = blockIdx.y, v0 = blockIdx.x * 16;
    int tid = threadIdx.x;
    for (int e = tid; e < 32 * 52; e += 256) {
        int c = e / 52, q = e - c * 52;
        *(float4*)&sx[c][q * 4] =
            *(const float4*)(x + (size_t)(b * 32 + c) * MCOLS + v0 * 13 + q * 4);
    }
    __syncthreads();
    for (int e = tid; e < 208 * 4; e += 256) {
        int n = e >> 2, ch = e & 3;
        union { uint4 u; __half2 h[4]; } pk;
#pragma unroll
        for (int i = 0; i < 4; i++)
            pk.h[i] = __floats2half2_rn(sx[ch * 8 + 2 * i][n], sx[ch * 8 + 2 * i + 1][n]);
        *(uint4*)(g_Xt + ((size_t)b * MCOLS + v0 * 13 + n) * 32 + ch * 8) = pk.u;
    }
    for (int e = tid; e < 416 * 2; e += 256) {
        int r = e >> 1, vi0 = (e & 1) * 8;
        int l = r >> 5, c = r & 31;
        union { uint4 u; __half2 h[4]; } pk;
#pragma unroll
        for (int i = 0; i < 4; i++)
            pk.h[i] = __floats2half2_rn(sx[c][(vi0 + 2 * i) * 13 + l],
                                        sx[c][(vi0 + 2 * i + 1) * 13 + l]);
        *(uint4*)(g_Xh + (size_t)(b * 416 + r) * 1024 + v0 + vi0) = pk.u;
    }
}

__global__ void k_convW(const float* __restrict__ W) {
    int idx = blockIdx.x * 256 + threadIdx.x;
    if (idx >= 64 * CIN) return;
    g_Wh[idx] = __float2half(W[idx]);
}

// ---------------- gemm0: (A^T)^2 exact 2-term, BM=128 BN=128, 2-stage, 96KB ----------------
#define STAGE_B0 49152          // Ah 16K | Al 16K | B 16K
#define GEMM_DYN0 (2 * STAGE_B0)

__global__ __launch_bounds__(256, 2) void k_gemm0() {
    extern __shared__ char sm[];
    const uint32_t sbase = smem_u32(sm);
    const int tid = threadIdx.x, lane = tid & 31, wid = tid >> 5;

    int s = blockIdx.z;
    const __half* Ah = g_Abf_h + (size_t)(s * 2048) * 1024;
    const __half* Al = g_Abf_l + (size_t)(s * 2048) * 1024;
    const __half* Bh = g_Bh + ((size_t)s << 20);
    const size_t i0 = (size_t)blockIdx.x * 128;
    const size_t j0 = (size_t)blockIdx.y * 128;

    const int wm = (wid & 1) * 64;
    const int wn = (wid >> 1) * 32;
    const int arow = wm + (lane & 15);
    const int a_x7 = arow & 7;
    const int a_cs = lane >> 4;
    const int brow = wn + ((lane >> 4) << 3) + (lane & 7);
    const int b_x7 = brow & 7;
    const int b_cs = (lane >> 3) & 1;

    float acc[4][4][4];
#pragma unroll
    for (int mt = 0; mt < 4; mt++)
#pragma unroll
        for (int nt = 0; nt < 4; nt++)
#pragma unroll
            for (int q = 0; q < 4; q++) acc[mt][nt][q] = 0.f;

    auto load_stage = [&](int st, int buf) {
        const int kv0 = st * 64;
        const uint32_t sb = sbase + buf * STAGE_B0;
#pragma unroll
        for (int q = 0; q < 4; q++) {
            int id = tid + 256 * q;
            int row = id >> 3, kc = id & 7;
            uint32_t sw = row * 128 + ((kc ^ (row & 7)) << 4);
            size_t go = (i0 + row) * 1024 + kv0 + kc * 8;
            CP16(sb + sw, Ah + go);
            CP16(sb + 16384 + sw, Al + go);
            CP16(sb + 32768 + sw, Bh + (j0 + row) * 1024 + kv0 + kc * 8);
        }
    };

    load_stage(0, 0); CP_COMMIT();
    load_stage(1, 1); CP_COMMIT();

    for (int st = 0; st < 16; ++st) {
        CP_WAIT1();
        __syncthreads();
        const int buf = st & 1;
        const uint32_t sb = sbase + buf * STAGE_B0;
#pragma unroll
        for (int kk = 0; kk < 4; kk++) {
            uint32_t ah[4][4], al[4][4];
#pragma unroll
            for (int mt = 0; mt < 4; mt++) {
                uint32_t addr = sb + (arow + mt * 16) * 128 + (((kk * 2 + a_cs) ^ a_x7) << 4);
                LDSM4(ah[mt], addr);
                LDSM4(al[mt], addr + 16384);
            }
#pragma unroll
            for (int nt2 = 0; nt2 < 2; nt2++) {
                uint32_t bh[4];
                LDSM4(bh, sb + 32768 + (brow + nt2 * 16) * 128 +
                          (((kk * 2 + b_cs) ^ b_x7) << 4));
#pragma unroll
                for (int mt = 0; mt < 4; mt++) {
                    MMAH(acc[mt][nt2 * 2],     ah[mt], bh[0], bh[1]);
                    MMAH(acc[mt][nt2 * 2 + 1], ah[mt], bh[2], bh[3]);
                    MMAH(acc[mt][nt2 * 2],     al[mt], bh[0], bh[1]);
                    MMAH(acc[mt][nt2 * 2 + 1], al[mt], bh[2], bh[3]);
                }
            }
        }
        __syncthreads();
        if (st + 2 < 16) load_stage(st + 2, buf);
        CP_COMMIT();
    }

    // fp16 epilogue into squared rows of g_Abf_h
    const int crow = lane >> 2;
    const int ccol = (lane & 3) * 2;
    __half* C = g_Abf_h + (size_t)(s * 2048 + 1024) * 1024;
#pragma unroll
    for (int mt = 0; mt < 4; mt++) {
        size_t rbase = (i0 + wm + mt * 16 + crow) * 1024 + j0 + wn + ccol;
#pragma unroll
        for (int nt = 0; nt < 4; nt++) {
            __half* p = C + rbase + nt * 8;
            *(__half2*)p              = __floats2half2_rn(acc[mt][nt][0], acc[mt][nt][1]);
            *(__half2*)(p + 8 * 1024) = __floats2half2_rn(acc[mt][nt][2], acc[mt][nt][3]);
        }
    }
}

// ---------------- gemm1: diffusion 1-term, BM=128 BN=128, 2 CTAs/SM ----------------
// half = 0: first-order rows; half = 1: squared rows.
#define STAGE_B1 32768
#define GEMM_DYN1 (3 * STAGE_B1)

__global__ __launch_bounds__(256, 2) void k_gemm1(int half) {
    extern __shared__ char sm[];
    const uint32_t sbase = smem_u32(sm);
    const int tid = threadIdx.x, lane = tid & 31, wid = tid >> 5;

    const size_t i0 = (size_t)(((blockIdx.x >> 3) * 16) + half * 8 + (blockIdx.x & 7)) * 128;
    const size_t j0 = (size_t)blockIdx.y * 128;

    const int wm = (wid & 1) * 64;
    const int wn = (wid >> 1) * 32;
    const int arow = wm + (lane & 15);
    const int a_x7 = arow & 7;
    const int a_cs = lane >> 4;
    const int brow = wn + ((lane >> 4) << 3) + (lane & 7);
    const int b_x7 = brow & 7;
    const int b_cs = (lane >> 3) & 1;

    float acc[4][4][4];
#pragma unroll
    for (int mt = 0; mt < 4; mt++)
#pragma unroll
        for (int nt = 0; nt < 4; nt++)
#pragma unroll
            for (int q = 0; q < 4; q++) acc[mt][nt][q] = 0.f;

    auto load_stage = [&](int st, int buf) {
        const int kv0 = st * 64;
        const uint32_t sb = sbase + buf * STAGE_B1;
#pragma unroll
        for (int q = 0; q < 4; q++) {
            int id = tid + 256 * q;
            int row = id >> 3, kc = id & 7;
            uint32_t sw = row * 128 + ((kc ^ (row & 7)) << 4);
            CP16(sb + sw, g_Abf_h + (i0 + row) * 1024 + kv0 + kc * 8);
        }
#pragma unroll
        for (int q = 0; q < 4; q++) {
            int id = tid + 256 * q;
            int row = id >> 3, kc = id & 7;
            uint32_t sw = row * 128 + ((kc ^ (row & 7)) << 4);
            CP16(sb + 16384 + sw, g_Xh + (j0 + row) * 1024 + kv0 + kc * 8);
        }
    };

    load_stage(0, 0); CP_COMMIT();
    load_stage(1, 1); CP_COMMIT();
    load_stage(2, 2); CP_COMMIT();

    int buf = 0;
    for (int st = 0; st < 16; ++st) {
        CP_WAIT2();
        __syncthreads();
        const uint32_t sb = sbase + buf * STAGE_B1;
#pragma unroll
        for (int kk = 0; kk < 4; kk++) {
            uint32_t ah[4][4];
#pragma unroll
            for (int mt = 0; mt < 4; mt++)
                LDSM4(ah[mt], sb + (arow + mt * 16) * 128 + (((kk * 2 + a_cs) ^ a_x7) << 4));
#pragma unroll
            for (int nt2 = 0; nt2 < 2; nt2++) {
                uint32_t bh[4];
                LDSM4(bh, sb + 16384 + (brow + nt2 * 16) * 128 +
                          (((kk * 2 + b_cs) ^ b_x7) << 4));
#pragma unroll
                for (int mt = 0; mt < 4; mt++) {
                    MMAH(acc[mt][nt2 * 2],     ah[mt], bh[0], bh[1]);
                    MMAH(acc[mt][nt2 * 2 + 1], ah[mt], bh[2], bh[3]);
                }
            }
        }
        __syncthreads();
        if (st + 3 < 16) load_stage(st + 3, buf);
        CP_COMMIT();
        buf = (buf + 1 == 3) ? 0 : buf + 1;
    }

    const int crow = lane >> 2;
    const int ccol = (lane & 3) * 2;
#pragma unroll
    for (int mt = 0; mt < 4; mt++) {
        size_t rbase = (i0 + wm + mt * 16 + crow) * MCOLS + j0 + wn + ccol;
#pragma unroll
        for (int nt = 0; nt < 4; nt++) {
            __half* p = g_yt + rbase + nt * 8;
            *(__half2*)p               = __floats2half2_rn(acc[mt][nt][0], acc[mt][nt][1]);
            *(__half2*)(p + 8 * MCOLS) = __floats2half2_rn(acc[mt][nt][2], acc[mt][nt][3]);
        }
    }
}

// ---------------- final MMA: out = Wh * H + bias (pipelined staging) ----------------
#define FIN_W    0
#define FIN_HS   (64 * PAD_E * 2)
#define FIN_DYN  (FIN_HS + 128 * PAD_E * 2)

__global__ __launch_bounds__(256, 2) void k_final(const float* __restrict__ bias,
                                                  float* __restrict__ out) {
    extern __shared__ char sm[];
    const uint32_t sbase = smem_u32(sm);
    const int tid = threadIdx.x, lane = tid & 31, wid = tid >> 5;
    const int b = blockIdx.y;
    const int j0 = blockIdx.x * 128;

    for (int e = tid; e < 64 * 28; e += 256) {
        int r = e / 28, q = e - r * 28;
        CP16(sbase + FIN_W + r * 464 + q * 16, g_Wh + r * CIN + q * 8);
    }
    for (int e = tid; e < 128 * 14; e += 256) {
        int r = e / 14, q = e - r * 14;
        int n = j0 + r;
        int v = n / 13, l = n - v * 13;
        const __half* src;
        if (q < 4)
            src = g_Xt + ((size_t)b * MCOLS + n) * 32 + q * 8;
        else {
            int g = (q - 4) >> 2, ch = (q - 4) & 3;
            src = g_yt + ((size_t)(g * 1024 + v)) * MCOLS + b * 416 + l * 32 + ch * 8;
        }
        CP16(sbase + FIN_HS + r * 464 + q * 16, src);
    }
    CP_COMMIT();
    for (int e = tid; e < 128 * 14; e += 256) {
        int r = e / 14, q = 14 + (e - r * 14);
        int n = j0 + r;
        int v = n / 13, l = n - v * 13;
        int g = (q - 4) >> 2, ch = (q - 4) & 3;
        const __half* src = g_yt + ((size_t)(g * 1024 + v)) * MCOLS + b * 416 + l * 32 + ch * 8;
        CP16(sbase + FIN_HS + r * 464 + q * 16, src);
    }
    CP_COMMIT();

    const int wm = (wid & 1) * 32;
    const int wn = (wid >> 1) * 32;
    const int arow_l = lane & 15;
    const int a_cs = lane >> 4;
    const int brow_l = ((lane >> 4) << 3) + (lane & 7);
    const int b_cs = (lane >> 3) & 1;

    float acc[2][4][4];
#pragma unroll
    for (int mt = 0; mt < 2; mt++)
#pragma unroll
        for (int nt = 0; nt < 4; nt++)
#pragma unroll
            for (int q = 0; q < 4; q++) acc[mt][nt][q] = 0.f;

    CP_WAIT1();
    __syncthreads();

#pragma unroll
    for (int kc = 0; kc < 7; kc++) {
        uint32_t wh[2][4];
#pragma unroll
        for (int mt = 0; mt < 2; mt++)
            LDSM4(wh[mt], sbase + FIN_W + (wm + mt * 16 + arow_l) * 464 + (kc * 2 + a_cs) * 16);
#pragma unroll
        for (int nt2 = 0; nt2 < 2; nt2++) {
            uint32_t bh[4];
            LDSM4(bh, sbase + FIN_HS + (wn + nt2 * 16 + brow_l) * 464 +
                      (kc * 2 + b_cs) * 16);
#pragma unroll
            for (int mt = 0; mt < 2; mt++) {
                MMAH(acc[mt][nt2 * 2],     wh[mt], bh[0], bh[1]);
                MMAH(acc[mt][nt2 * 2 + 1], wh[mt], bh[2], bh[3]);
            }
        }
    }

    CP_WAIT0();
    __syncthreads();

#pragma unroll
    for (int kc = 7; kc < 14; kc++) {
        uint32_t wh[2][4];
#pragma unroll
        for (int mt = 0; mt < 2; mt++)
            LDSM4(wh[mt], sbase + FIN_W + (wm + mt * 16 + arow_l) * 464 + (kc * 2 + a_cs) * 16);
#pragma unroll
        for (int nt2 = 0; nt2 < 2; nt2++) {
            uint32_t bh[4];
            LDSM4(bh, sbase + FIN_HS + (wn + nt2 * 16 + brow_l) * 464 +
                      (kc * 2 + b_cs) * 16);
#pragma unroll
            for (int mt = 0; mt < 2; mt++) {
                MMAH(acc[mt][nt2 * 2],     wh[mt], bh[0], bh[1]);
                MMAH(acc[mt][nt2 * 2 + 1], wh[mt], bh[2], bh[3]);
            }
        }
    }

    const int crow = lane >> 2;
    const int ccol = (lane & 3) * 2;
#pragma unroll
    for (int mt = 0; mt < 2; mt++) {
        int o = wm + mt * 16 + crow;
        float b0 = bias[o], b1 = bias[o + 8];
        size_t r0 = (size_t)(b * 64 + o) * MCOLS + j0 + wn + ccol;
#pragma unroll
        for (int nt = 0; nt < 4; nt++) {
            float* p = out + r0 + nt * 8;
            *(float2*)p               = make_float2(acc[mt][nt][0] + b0, acc[mt][nt][1] + b0);
            *(float2*)(p + 8 * MCOLS) = make_float2(acc[mt][nt][2] + b1, acc[mt][nt][3] + b1);
        }
    }
}

// ---------------- launcher: fork-join overlap ----------------
extern "C" void kernel_launch(void* const* d_in, const int* in_sizes, int n_in,
                              void* d_out, int out_size) {
    const float* x    = (const float*)d_in[0];
    const float* A0   = (const float*)d_in[1];
    const float* A1   = (const float*)d_in[2];
    const float* A2   = (const float*)d_in[3];
    const float* W    = (const float*)d_in[4];
    const float* bias = (const float*)d_in[5];
    float* out = (float*)d_out;

    static cudaStream_t s2 = nullptr;
    static cudaEvent_t e0 = nullptr, eA = nullptr, eJ = nullptr;
    if (!s2) {
        cudaStreamCreateWithFlags(&s2, cudaStreamNonBlocking);
        cudaEventCreateWithFlags(&e0, cudaEventDisableTiming);
        cudaEventCreateWithFlags(&eA, cudaEventDisableTiming);
        cudaEventCreateWithFlags(&eJ, cudaEventDisableTiming);
        cudaFuncSetAttribute(k_gemm0, cudaFuncAttributeMaxDynamicSharedMemorySize, GEMM_DYN0);
        cudaFuncSetAttribute(k_gemm1, cudaFuncAttributeMaxDynamicSharedMemorySize, GEMM_DYN1);
        cudaFuncSetAttribute(k_final, cudaFuncAttributeMaxDynamicSharedMemorySize, FIN_DYN);
    }

    // fork: side stream joins the capture
    cudaEventRecord(e0, 0);
    cudaStreamWaitEvent(s2, e0, 0);

    // side stream: stageX, convW (independent of A)
    k_stageX<<<dim3(64, 32), 256, 0, s2>>>(x);
    k_convW<<<56, 256, 0, s2>>>(W);

    // main stream: stageA, then gemm0 (96KB -> co-resident with gemm1a)
    k_stageA<<<dim3(32, 32, 3), dim3(32, 8)>>>(A0, A1, A2);
    cudaEventRecord(eA, 0);
    k_gemm0<<<dim3(8, 8, 3), 256, GEMM_DYN0>>>();

    // side stream: first-order diffusion tiles (need stageA + stageX, NOT gemm0)
    cudaStreamWaitEvent(s2, eA, 0);
    k_gemm1<<<dim3(24, 104), 256, GEMM_DYN1, s2>>>(0);
    cudaEventRecord(eJ, s2);

    // join, then squared-row diffusion tiles (need gemm0 + stageX)
    cudaStreamWaitEvent(0, eJ, 0);
    k_gemm1<<<dim3(24, 104), 256, GEMM_DYN1>>>(1);

    k_final<<<dim3(104, 32), 256, FIN_DYN>>>(bias, out);
}

// round 15
// speedup vs baseline: 1.1692x; 1.0143x over previous
#include <cuda_runtime.h>
#include <cuda_fp16.h>
#include <cstdint>

// GraphConvNet: B=32, C=32, V=1024, L=13, support=3, order=2
// R14 + column-group pipelining: gemm1 (both halves) and k_final split into 8
// batch-groups (4 b = 13 j-tiles each); k_final groups overlap gemm1 tail.

#define V_N   1024
#define MCOLS 13312
#define MI    6144
#define CIN   224
#define NB    32
#define PAD_E 232

// ---------------- scratch ----------------
__device__ __align__(16) __half g_yt [(size_t)MI * MCOLS];      // [i=(g,v)][m'=(b,l,c)]
__device__ __align__(16) __half g_Abf_h[(size_t)MI * V_N];
__device__ __align__(16) __half g_Abf_l[(size_t)MI * V_N];
__device__ __align__(16) __half g_Bh [3u * 1024u * 1024u];
__device__ __align__(16) __half g_Xh [(size_t)MCOLS * V_N];     // [m'=(b,l,c)][v]
__device__ __align__(16) __half g_Xt [(size_t)NB * MCOLS * 32]; // [(b,v,l)][c]
__device__ __align__(16) __half g_Wh [64 * CIN];

// ================= helpers =================
__device__ __forceinline__ uint32_t smem_u32(const void* p) {
    uint32_t a;
    asm("{ .reg .u64 t; cvta.to.shared.u64 t, %1; cvt.u32.u64 %0, t; }" : "=r"(a) : "l"(p));
    return a;
}
#define CP16(s, g) asm volatile("cp.async.cg.shared.global [%0], [%1], 16;" :: "r"(s), "l"(g))
#define CP_COMMIT() asm volatile("cp.async.commit_group;")
#define CP_WAIT2()  asm volatile("cp.async.wait_group 2;")
#define CP_WAIT1()  asm volatile("cp.async.wait_group 1;")
#define CP_WAIT0()  asm volatile("cp.async.wait_group 0;")

#define LDSM4(r, addr)                                                          \
    asm volatile("ldmatrix.sync.aligned.m8n8.x4.shared.b16 {%0,%1,%2,%3}, [%4];"\
        : "=r"((r)[0]), "=r"((r)[1]), "=r"((r)[2]), "=r"((r)[3]) : "r"(addr))

#define MMAH(d, a, b0, b1)                                                      \
    asm volatile("mma.sync.aligned.m16n8k16.row.col.f32.f16.f16.f32 "           \
        "{%0,%1,%2,%3},{%4,%5,%6,%7},{%8,%9},{%0,%1,%2,%3};"                    \
        : "+f"((d)[0]), "+f"((d)[1]), "+f"((d)[2]), "+f"((d)[3])                \
        : "r"((a)[0]), "r"((a)[1]), "r"((a)[2]), "r"((a)[3]), "r"(b0), "r"(b1))

// ---------------- A: transpose+split-convert + direct fp16 copy ----------------
__global__ void k_stageA(const float* __restrict__ A0, const float* __restrict__ A1,
                         const float* __restrict__ A2) {
    __shared__ float t[32][33];
    int s = blockIdx.z;
    const float* A = (s == 0) ? A0 : ((s == 1) ? A1 : A2);
    int wb = blockIdx.x * 32, vb = blockIdx.y * 32;
#pragma unroll
    for (int j = 0; j < 32; j += 8) {
        float f = A[(size_t)(vb + threadIdx.y + j) * 1024 + wb + threadIdx.x];
        t[threadIdx.y + j][threadIdx.x] = f;
        g_Bh[((size_t)s << 20) + (size_t)(vb + threadIdx.y + j) * 1024 + wb + threadIdx.x] =
            __float2half(f);
    }
    __syncthreads();
#pragma unroll
    for (int j = 0; j < 32; j += 8) {
        float f = t[threadIdx.x][threadIdx.y + j];
        __half h = __float2half(f);
        size_t o = (size_t)(s * 2048 + wb + threadIdx.y + j) * 1024 + vb + threadIdx.x;
        g_Abf_h[o] = h;
        g_Abf_l[o] = __float2half(f - __half2float(h));
    }
}

// ---------------- x -> g_Xh[m'][v] and g_Xt[(b,v,l)][c] ----------------
__global__ __launch_bounds__(256) void k_stageX(const float* __restrict__ x) {
    __shared__ float sx[32][212];
    int b = blockIdx.y, v0 = blockIdx.x * 16;
    int tid = threadIdx.x;
    for (int e = tid; e < 32 * 52; e += 256) {
        int c = e / 52, q = e - c * 52;
        *(float4*)&sx[c][q * 4] =
            *(const float4*)(x + (size_t)(b * 32 + c) * MCOLS + v0 * 13 + q * 4);
    }
    __syncthreads();
    for (int e = tid; e < 208 * 4; e += 256) {
        int n = e >> 2, ch = e & 3;
        union { uint4 u; __half2 h[4]; } pk;
#pragma unroll
        for (int i = 0; i < 4; i++)
            pk.h[i] = __floats2half2_rn(sx[ch * 8 + 2 * i][n], sx[ch * 8 + 2 * i + 1][n]);
        *(uint4*)(g_Xt + ((size_t)b * MCOLS + v0 * 13 + n) * 32 + ch * 8) = pk.u;
    }
    for (int e = tid; e < 416 * 2; e += 256) {
        int r = e >> 1, vi0 = (e & 1) * 8;
        int l = r >> 5, c = r & 31;
        union { uint4 u; __half2 h[4]; } pk;
#pragma unroll
        for (int i = 0; i < 4; i++)
            pk.h[i] = __floats2half2_rn(sx[c][(vi0 + 2 * i) * 13 + l],
                                        sx[c][(vi0 + 2 * i + 1) * 13 + l]);
        *(uint4*)(g_Xh + (size_t)(b * 416 + r) * 1024 + v0 + vi0) = pk.u;
    }
}

__global__ void k_convW(const float* __restrict__ W) {
    int idx = blockIdx.x * 256 + threadIdx.x;
    if (idx >= 64 * CIN) return;
    g_Wh[idx] = __float2half(W[idx]);
}

// ---------------- gemm0: (A^T)^2 exact 2-term, BM=128 BN=128, 2-stage, 96KB ----------------
#define STAGE_B0 49152
#define GEMM_DYN0 (2 * STAGE_B0)

__global__ __launch_bounds__(256, 2) void k_gemm0() {
    extern __shared__ char sm[];
    const uint32_t sbase = smem_u32(sm);
    const int tid = threadIdx.x, lane = tid & 31, wid = tid >> 5;

    int s = blockIdx.z;
    const __half* Ah = g_Abf_h + (size_t)(s * 2048) * 1024;
    const __half* Al = g_Abf_l + (size_t)(s * 2048) * 1024;
    const __half* Bh = g_Bh + ((size_t)s << 20);
    const size_t i0 = (size_t)blockIdx.x * 128;
    const size_t j0 = (size_t)blockIdx.y * 128;

    const int wm = (wid & 1) * 64;
    const int wn = (wid >> 1) * 32;
    const int arow = wm + (lane & 15);
    const int a_x7 = arow & 7;
    const int a_cs = lane >> 4;
    const int brow = wn + ((lane >> 4) << 3) + (lane & 7);
    const int b_x7 = brow & 7;
    const int b_cs = (lane >> 3) & 1;

    float acc[4][4][4];
#pragma unroll
    for (int mt = 0; mt < 4; mt++)
#pragma unroll
        for (int nt = 0; nt < 4; nt++)
#pragma unroll
            for (int q = 0; q < 4; q++) acc[mt][nt][q] = 0.f;

    auto load_stage = [&](int st, int buf) {
        const int kv0 = st * 64;
        const uint32_t sb = sbase + buf * STAGE_B0;
#pragma unroll
        for (int q = 0; q < 4; q++) {
            int id = tid + 256 * q;
            int row = id >> 3, kc = id & 7;
            uint32_t sw = row * 128 + ((kc ^ (row & 7)) << 4);
            size_t go = (i0 + row) * 1024 + kv0 + kc * 8;
            CP16(sb + sw, Ah + go);
            CP16(sb + 16384 + sw, Al + go);
            CP16(sb + 32768 + sw, Bh + (j0 + row) * 1024 + kv0 + kc * 8);
        }
    };

    load_stage(0, 0); CP_COMMIT();
    load_stage(1, 1); CP_COMMIT();

    for (int st = 0; st < 16; ++st) {
        CP_WAIT1();
        __syncthreads();
        const int buf = st & 1;
        const uint32_t sb = sbase + buf * STAGE_B0;
#pragma unroll
        for (int kk = 0; kk < 4; kk++) {
            uint32_t ah[4][4], al[4][4];
#pragma unroll
            for (int mt = 0; mt < 4; mt++) {
                uint32_t addr = sb + (arow + mt * 16) * 128 + (((kk * 2 + a_cs) ^ a_x7) << 4);
                LDSM4(ah[mt], addr);
                LDSM4(al[mt], addr + 16384);
            }
#pragma unroll
            for (int nt2 = 0; nt2 < 2; nt2++) {
                uint32_t bh[4];
                LDSM4(bh, sb + 32768 + (brow + nt2 * 16) * 128 +
                          (((kk * 2 + b_cs) ^ b_x7) << 4));
#pragma unroll
                for (int mt = 0; mt < 4; mt++) {
                    MMAH(acc[mt][nt2 * 2],     ah[mt], bh[0], bh[1]);
                    MMAH(acc[mt][nt2 * 2 + 1], ah[mt], bh[2], bh[3]);
                    MMAH(acc[mt][nt2 * 2],     al[mt], bh[0], bh[1]);
                    MMAH(acc[mt][nt2 * 2 + 1], al[mt], bh[2], bh[3]);
                }
            }
        }
        __syncthreads();
        if (st + 2 < 16) load_stage(st + 2, buf);
        CP_COMMIT();
    }

    const int crow = lane >> 2;
    const int ccol = (lane & 3) * 2;
    __half* C = g_Abf_h + (size_t)(s * 2048 + 1024) * 1024;
#pragma unroll
    for (int mt = 0; mt < 4; mt++) {
        size_t rbase = (i0 + wm + mt * 16 + crow) * 1024 + j0 + wn + ccol;
#pragma unroll
        for (int nt = 0; nt < 4; nt++) {
            __half* p = C + rbase + nt * 8;
            *(__half2*)p              = __floats2half2_rn(acc[mt][nt][0], acc[mt][nt][1]);
            *(__half2*)(p + 8 * 1024) = __floats2half2_rn(acc[mt][nt][2], acc[mt][nt][3]);
        }
    }
}

// ---------------- gemm1: diffusion 1-term, BM=128 BN=128, 2 CTAs/SM ----------------
// half = 0: first-order rows; half = 1: squared rows. jof = first j-tile of this group.
#define STAGE_B1 32768
#define GEMM_DYN1 (3 * STAGE_B1)

__global__ __launch_bounds__(256, 2) void k_gemm1(int half, int jof) {
    extern __shared__ char sm[];
    const uint32_t sbase = smem_u32(sm);
    const int tid = threadIdx.x, lane = tid & 31, wid = tid >> 5;

    const size_t i0 = (size_t)(((blockIdx.x >> 3) * 16) + half * 8 + (blockIdx.x & 7)) * 128;
    const size_t j0 = (size_t)(jof + blockIdx.y) * 128;

    const int wm = (wid & 1) * 64;
    const int wn = (wid >> 1) * 32;
    const int arow = wm + (lane & 15);
    const int a_x7 = arow & 7;
    const int a_cs = lane >> 4;
    const int brow = wn + ((lane >> 4) << 3) + (lane & 7);
    const int b_x7 = brow & 7;
    const int b_cs = (lane >> 3) & 1;

    float acc[4][4][4];
#pragma unroll
    for (int mt = 0; mt < 4; mt++)
#pragma unroll
        for (int nt = 0; nt < 4; nt++)
#pragma unroll
            for (int q = 0; q < 4; q++) acc[mt][nt][q] = 0.f;

    auto load_stage = [&](int st, int buf) {
        const int kv0 = st * 64;
        const uint32_t sb = sbase + buf * STAGE_B1;
#pragma unroll
        for (int q = 0; q < 4; q++) {
            int id = tid + 256 * q;
            int row = id >> 3, kc = id & 7;
            uint32_t sw = row * 128 + ((kc ^ (row & 7)) << 4);
            CP16(sb + sw, g_Abf_h + (i0 + row) * 1024 + kv0 + kc * 8);
        }
#pragma unroll
        for (int q = 0; q < 4; q++) {
            int id = tid + 256 * q;
            int row = id >> 3, kc = id & 7;
            uint32_t sw = row * 128 + ((kc ^ (row & 7)) << 4);
            CP16(sb + 16384 + sw, g_Xh + (j0 + row) * 1024 + kv0 + kc * 8);
        }
    };

    load_stage(0, 0); CP_COMMIT();
    load_stage(1, 1); CP_COMMIT();
    load_stage(2, 2); CP_COMMIT();

    int buf = 0;
    for (int st = 0; st < 16; ++st) {
        CP_WAIT2();
        __syncthreads();
        const uint32_t sb = sbase + buf * STAGE_B1;
#pragma unroll
        for (int kk = 0; kk < 4; kk++) {
            uint32_t ah[4][4];
#pragma unroll
            for (int mt = 0; mt < 4; mt++)
                LDSM4(ah[mt], sb + (arow + mt * 16) * 128 + (((kk * 2 + a_cs) ^ a_x7) << 4));
#pragma unroll
            for (int nt2 = 0; nt2 < 2; nt2++) {
                uint32_t bh[4];
                LDSM4(bh, sb + 16384 + (brow + nt2 * 16) * 128 +
                          (((kk * 2 + b_cs) ^ b_x7) << 4));
#pragma unroll
                for (int mt = 0; mt < 4; mt++) {
                    MMAH(acc[mt][nt2 * 2],     ah[mt], bh[0], bh[1]);
                    MMAH(acc[mt][nt2 * 2 + 1], ah[mt], bh[2], bh[3]);
                }
            }
        }
        __syncthreads();
        if (st + 3 < 16) load_stage(st + 3, buf);
        CP_COMMIT();
        buf = (buf + 1 == 3) ? 0 : buf + 1;
    }

    const int crow = lane >> 2;
    const int ccol = (lane & 3) * 2;
#pragma unroll
    for (int mt = 0; mt < 4; mt++) {
        size_t rbase = (i0 + wm + mt * 16 + crow) * MCOLS + j0 + wn + ccol;
#pragma unroll
        for (int nt = 0; nt < 4; nt++) {
            __half* p = g_yt + rbase + nt * 8;
            *(__half2*)p               = __floats2half2_rn(acc[mt][nt][0], acc[mt][nt][1]);
            *(__half2*)(p + 8 * MCOLS) = __floats2half2_rn(acc[mt][nt][2], acc[mt][nt][3]);
        }
    }
}

// ---------------- final MMA: out = Wh * H + bias (pipelined staging), per-batch-group ----------------
#define FIN_W    0
#define FIN_HS   (64 * PAD_E * 2)
#define FIN_DYN  (FIN_HS + 128 * PAD_E * 2)

__global__ __launch_bounds__(256, 2) void k_final(const float* __restrict__ bias,
                                                  float* __restrict__ out, int bof) {
    extern __shared__ char sm[];
    const uint32_t sbase = smem_u32(sm);
    const int tid = threadIdx.x, lane = tid & 31, wid = tid >> 5;
    const int b = bof + blockIdx.y;
    const int j0 = blockIdx.x * 128;

    for (int e = tid; e < 64 * 28; e += 256) {
        int r = e / 28, q = e - r * 28;
        CP16(sbase + FIN_W + r * 464 + q * 16, g_Wh + r * CIN + q * 8);
    }
    for (int e = tid; e < 128 * 14; e += 256) {
        int r = e / 14, q = e - r * 14;
        int n = j0 + r;
        int v = n / 13, l = n - v * 13;
        const __half* src;
        if (q < 4)
            src = g_Xt + ((size_t)b * MCOLS + n) * 32 + q * 8;
        else {
            int g = (q - 4) >> 2, ch = (q - 4) & 3;
            src = g_yt + ((size_t)(g * 1024 + v)) * MCOLS + b * 416 + l * 32 + ch * 8;
        }
        CP16(sbase + FIN_HS + r * 464 + q * 16, src);
    }
    CP_COMMIT();
    for (int e = tid; e < 128 * 14; e += 256) {
        int r = e / 14, q = 14 + (e - r * 14);
        int n = j0 + r;
        int v = n / 13, l = n - v * 13;
        int g = (q - 4) >> 2, ch = (q - 4) & 3;
        const __half* src = g_yt + ((size_t)(g * 1024 + v)) * MCOLS + b * 416 + l * 32 + ch * 8;
        CP16(sbase + FIN_HS + r * 464 + q * 16, src);
    }
    CP_COMMIT();

    const int wm = (wid & 1) * 32;
    const int wn = (wid >> 1) * 32;
    const int arow_l = lane & 15;
    const int a_cs = lane >> 4;
    const int brow_l = ((lane >> 4) << 3) + (lane & 7);
    const int b_cs = (lane >> 3) & 1;

    float acc[2][4][4];
#pragma unroll
    for (int mt = 0; mt < 2; mt++)
#pragma unroll
        for (int nt = 0; nt < 4; nt++)
#pragma unroll
            for (int q = 0; q < 4; q++) acc[mt][nt][q] = 0.f;

    CP_WAIT1();
    __syncthreads();

#pragma unroll
    for (int kc = 0; kc < 7; kc++) {
        uint32_t wh[2][4];
#pragma unroll
        for (int mt = 0; mt < 2; mt++)
            LDSM4(wh[mt], sbase + FIN_W + (wm + mt * 16 + arow_l) * 464 + (kc * 2 + a_cs) * 16);
#pragma unroll
        for (int nt2 = 0; nt2 < 2; nt2++) {
            uint32_t bh[4];
            LDSM4(bh, sbase + FIN_HS + (wn + nt2 * 16 + brow_l) * 464 +
                      (kc * 2 + b_cs) * 16);
#pragma unroll
            for (int mt = 0; mt < 2; mt++) {
                MMAH(acc[mt][nt2 * 2],     wh[mt], bh[0], bh[1]);
                MMAH(acc[mt][nt2 * 2 + 1], wh[mt], bh[2], bh[3]);
            }
        }
    }

    CP_WAIT0();
    __syncthreads();

#pragma unroll
    for (int kc = 7; kc < 14; kc++) {
        uint32_t wh[2][4];
#pragma unroll
        for (int mt = 0; mt < 2; mt++)
            LDSM4(wh[mt], sbase + FIN_W + (wm + mt * 16 + arow_l) * 464 + (kc * 2 + a_cs) * 16);
#pragma unroll
        for (int nt2 = 0; nt2 < 2; nt2++) {
            uint32_t bh[4];
            LDSM4(bh, sbase + FIN_HS + (wn + nt2 * 16 + brow_l) * 464 +
                      (kc * 2 + b_cs) * 16);
#pragma unroll
            for (int mt = 0; mt < 2; mt++) {
                MMAH(acc[mt][nt2 * 2],     wh[mt], bh[0], bh[1]);
                MMAH(acc[mt][nt2 * 2 + 1], wh[mt], bh[2], bh[3]);
            }
        }
    }

    const int crow = lane >> 2;
    const int ccol = (lane & 3) * 2;
#pragma unroll
    for (int mt = 0; mt < 2; mt++) {
        int o = wm + mt * 16 + crow;
        float b0 = bias[o], b1 = bias[o + 8];
        size_t r0 = (size_t)(b * 64 + o) * MCOLS + j0 + wn + ccol;
#pragma unroll
        for (int nt = 0; nt < 4; nt++) {
            float* p = out + r0 + nt * 8;
            *(float2*)p               = make_float2(acc[mt][nt][0] + b0, acc[mt][nt][1] + b0);
            *(float2*)(p + 8 * MCOLS) = make_float2(acc[mt][nt][2] + b1, acc[mt][nt][3] + b1);
        }
    }
}

// ---------------- launcher: 3-stream pipelined fork-join ----------------
#define NGRP 8

extern "C" void kernel_launch(void* const* d_in, const int* in_sizes, int n_in,
                              void* d_out, int out_size) {
    const float* x    = (const float*)d_in[0];
    const float* A0   = (const float*)d_in[1];
    const float* A1   = (const float*)d_in[2];
    const float* A2   = (const float*)d_in[3];
    const float* W    = (const float*)d_in[4];
    const float* bias = (const float*)d_in[5];
    float* out = (float*)d_out;

    static cudaStream_t s2 = nullptr, s3 = nullptr;
    static cudaEvent_t e0, eA, eX, eF2, eF3;
    static cudaEvent_t ea[NGRP], eb[NGRP];
    if (!s2) {
        cudaStreamCreateWithFlags(&s2, cudaStreamNonBlocking);
        cudaStreamCreateWithFlags(&s3, cudaStreamNonBlocking);
        cudaEventCreateWithFlags(&e0, cudaEventDisableTiming);
        cudaEventCreateWithFlags(&eA, cudaEventDisableTiming);
        cudaEventCreateWithFlags(&eX, cudaEventDisableTiming);
        cudaEventCreateWithFlags(&eF2, cudaEventDisableTiming);
        cudaEventCreateWithFlags(&eF3, cudaEventDisableTiming);
        for (int g = 0; g < NGRP; g++) {
            cudaEventCreateWithFlags(&ea[g], cudaEventDisableTiming);
            cudaEventCreateWithFlags(&eb[g], cudaEventDisableTiming);
        }
        cudaFuncSetAttribute(k_gemm0, cudaFuncAttributeMaxDynamicSharedMemorySize, GEMM_DYN0);
        cudaFuncSetAttribute(k_gemm1, cudaFuncAttributeMaxDynamicSharedMemorySize, GEMM_DYN1);
        cudaFuncSetAttribute(k_final, cudaFuncAttributeMaxDynamicSharedMemorySize, FIN_DYN);
    }

    // fork
    cudaEventRecord(e0, 0);
    cudaStreamWaitEvent(s2, e0, 0);
    cudaStreamWaitEvent(s3, e0, 0);

    // s2: X staging (also produces g_Xt for k_final), W convert
    k_stageX<<<dim3(64, 32), 256, 0, s2>>>(x);
    k_convW<<<56, 256, 0, s2>>>(W);
    cudaEventRecord(eX, s2);

    // stream 0: A staging, then gemm0 (96KB, co-resident)
    k_stageA<<<dim3(32, 32, 3), dim3(32, 8)>>>(A0, A1, A2);
    cudaEventRecord(eA, 0);
    k_gemm0<<<dim3(8, 8, 3), 256, GEMM_DYN0>>>();

    // s2: gemm1a groups (need stageA; stageX in-order on s2)
    cudaStreamWaitEvent(s2, eA, 0);
    for (int g = 0; g < NGRP; g++) {
        k_gemm1<<<dim3(24, 13), 256, GEMM_DYN1, s2>>>(0, g * 13);
        cudaEventRecord(ea[g], s2);
    }
    cudaEventRecord(eF2, s2);

    // stream 0: gemm1b groups (after gemm0 in-order; need stageX for g_Xh)
    cudaStreamWaitEvent(0, eX, 0);
    for (int g = 0; g < NGRP; g++) {
        k_gemm1<<<dim3(24, 13), 256, GEMM_DYN1>>>(1, g * 13);
        cudaEventRecord(eb[g], 0);
    }

    // s3: k_final groups as their columns complete
    cudaStreamWaitEvent(s3, eX, 0);
    for (int g = 0; g < NGRP; g++) {
        cudaStreamWaitEvent(s3, ea[g], 0);
        cudaStreamWaitEvent(s3, eb[g], 0);
        k_final<<<dim3(104, 4), 256, FIN_DYN, s3>>>(bias, out, g * 4);
    }
    cudaEventRecord(eF3, s3);

    // join back to stream 0
    cudaStreamWaitEvent(0, eF2, 0);
    cudaStreamWaitEvent(0, eF3, 0);
}

// round 17
// speedup vs baseline: 1.1705x; 1.0012x over previous
#include <cuda_runtime.h>
#include <cuda_fp16.h>
#include <cstdint>

// GraphConvNet: B=32, C=32, V=1024, L=13, support=3, order=2
// R15 kernels (proven) + launcher refinements: earlier eX, convW on s3, s3 high priority.

#define V_N   1024
#define MCOLS 13312
#define MI    6144
#define CIN   224
#define NB    32
#define PAD_E 232

// ---------------- scratch ----------------
__device__ __align__(16) __half g_yt [(size_t)MI * MCOLS];      // [i=(g,v)][m'=(b,l,c)]
__device__ __align__(16) __half g_Abf_h[(size_t)MI * V_N];
__device__ __align__(16) __half g_Abf_l[(size_t)MI * V_N];
__device__ __align__(16) __half g_Bh [3u * 1024u * 1024u];
__device__ __align__(16) __half g_Xh [(size_t)MCOLS * V_N];     // [m'=(b,l,c)][v]
__device__ __align__(16) __half g_Xt [(size_t)NB * MCOLS * 32]; // [(b,v,l)][c]
__device__ __align__(16) __half g_Wh [64 * CIN];

// ================= helpers =================
__device__ __forceinline__ uint32_t smem_u32(const void* p) {
    uint32_t a;
    asm("{ .reg .u64 t; cvta.to.shared.u64 t, %1; cvt.u32.u64 %0, t; }" : "=r"(a) : "l"(p));
    return a;
}
#define CP16(s, g) asm volatile("cp.async.cg.shared.global [%0], [%1], 16;" :: "r"(s), "l"(g))
#define CP_COMMIT() asm volatile("cp.async.commit_group;")
#define CP_WAIT2()  asm volatile("cp.async.wait_group 2;")
#define CP_WAIT1()  asm volatile("cp.async.wait_group 1;")
#define CP_WAIT0()  asm volatile("cp.async.wait_group 0;")

#define LDSM4(r, addr)                                                          \
    asm volatile("ldmatrix.sync.aligned.m8n8.x4.shared.b16 {%0,%1,%2,%3}, [%4];"\
        : "=r"((r)[0]), "=r"((r)[1]), "=r"((r)[2]), "=r"((r)[3]) : "r"(addr))

#define MMAH(d, a, b0, b1)                                                      \
    asm volatile("mma.sync.aligned.m16n8k16.row.col.f32.f16.f16.f32 "           \
        "{%0,%1,%2,%3},{%4,%5,%6,%7},{%8,%9},{%0,%1,%2,%3};"                    \
        : "+f"((d)[0]), "+f"((d)[1]), "+f"((d)[2]), "+f"((d)[3])                \
        : "r"((a)[0]), "r"((a)[1]), "r"((a)[2]), "r"((a)[3]), "r"(b0), "r"(b1))

// ---------------- A: transpose+split-convert + direct fp16 copy ----------------
__global__ void k_stageA(const float* __restrict__ A0, const float* __restrict__ A1,
                         const float* __restrict__ A2) {
    __shared__ float t[32][33];
    int s = blockIdx.z;
    const float* A = (s == 0) ? A0 : ((s == 1) ? A1 : A2);
    int wb = blockIdx.x * 32, vb = blockIdx.y * 32;
#pragma unroll
    for (int j = 0; j < 32; j += 8) {
        float f = A[(size_t)(vb + threadIdx.y + j) * 1024 + wb + threadIdx.x];
        t[threadIdx.y + j][threadIdx.x] = f;
        g_Bh[((size_t)s << 20) + (size_t)(vb + threadIdx.y + j) * 1024 + wb + threadIdx.x] =
            __float2half(f);
    }
    __syncthreads();
#pragma unroll
    for (int j = 0; j < 32; j += 8) {
        float f = t[threadIdx.x][threadIdx.y + j];
        __half h = __float2half(f);
        size_t o = (size_t)(s * 2048 + wb + threadIdx.y + j) * 1024 + vb + threadIdx.x;
        g_Abf_h[o] = h;
        g_Abf_l[o] = __float2half(f - __half2float(h));
    }
}

// ---------------- x -> g_Xh[m'][v] and g_Xt[(b,v,l)][c] ----------------
__global__ __launch_bounds__(256) void k_stageX(const float* __restrict__ x) {
    __shared__ float sx[32][212];
    int b = blockIdx.y, v0 = blockIdx.x * 16;
    int tid = threadIdx.x;
    for (int e = tid; e < 32 * 52; e += 256) {
        int c = e / 52, q = e - c * 52;
        *(float4*)&sx[c][q * 4] =
            *(const float4*)(x + (size_t)(b * 32 + c) * MCOLS + v0 * 13 + q * 4);
    }
    __syncthreads();
    for (int e = tid; e < 208 * 4; e += 256) {
        int n = e >> 2, ch = e & 3;
        union { uint4 u; __half2 h[4]; } pk;
#pragma unroll
        for (int i = 0; i < 4; i++)
            pk.h[i] = __floats2half2_rn(sx[ch * 8 + 2 * i][n], sx[ch * 8 + 2 * i + 1][n]);
        *(uint4*)(g_Xt + ((size_t)b * MCOLS + v0 * 13 + n) * 32 + ch * 8) = pk.u;
    }
    for (int e = tid; e < 416 * 2; e += 256) {
        int r = e >> 1, vi0 = (e & 1) * 8;
        int l = r >> 5, c = r & 31;
        union { uint4 u; __half2 h[4]; } pk;
#pragma unroll
        for (int i = 0; i < 4; i++)
            pk.h[i] = __floats2half2_rn(sx[c][(vi0 + 2 * i) * 13 + l],
                                        sx[c][(vi0 + 2 * i + 1) * 13 + l]);
        *(uint4*)(g_Xh + (size_t)(b * 416 + r) * 1024 + v0 + vi0) = pk.u;
    }
}

__global__ void k_convW(const float* __restrict__ W) {
    int idx = blockIdx.x * 256 + threadIdx.x;
    if (idx >= 64 * CIN) return;
    g_Wh[idx] = __float2half(W[idx]);
}

// ---------------- gemm0: (A^T)^2 exact 2-term, BM=128 BN=128, 2-stage, 96KB ----------------
#define STAGE_B0 49152
#define GEMM_DYN0 (2 * STAGE_B0)

__global__ __launch_bounds__(256, 2) void k_gemm0() {
    extern __shared__ char sm[];
    const uint32_t sbase = smem_u32(sm);
    const int tid = threadIdx.x, lane = tid & 31, wid = tid >> 5;

    int s = blockIdx.z;
    const __half* Ah = g_Abf_h + (size_t)(s * 2048) * 1024;
    const __half* Al = g_Abf_l + (size_t)(s * 2048) * 1024;
    const __half* Bh = g_Bh + ((size_t)s << 20);
    const size_t i0 = (size_t)blockIdx.x * 128;
    const size_t j0 = (size_t)blockIdx.y * 128;

    const int wm = (wid & 1) * 64;
    const int wn = (wid >> 1) * 32;
    const int arow = wm + (lane & 15);
    const int a_x7 = arow & 7;
    const int a_cs = lane >> 4;
    const int brow = wn + ((lane >> 4) << 3) + (lane & 7);
    const int b_x7 = brow & 7;
    const int b_cs = (lane >> 3) & 1;

    float acc[4][4][4];
#pragma unroll
    for (int mt = 0; mt < 4; mt++)
#pragma unroll
        for (int nt = 0; nt < 4; nt++)
#pragma unroll
            for (int q = 0; q < 4; q++) acc[mt][nt][q] = 0.f;

    auto load_stage = [&](int st, int buf) {
        const int kv0 = st * 64;
        const uint32_t sb = sbase + buf * STAGE_B0;
#pragma unroll
        for (int q = 0; q < 4; q++) {
            int id = tid + 256 * q;
            int row = id >> 3, kc = id & 7;
            uint32_t sw = row * 128 + ((kc ^ (row & 7)) << 4);
            size_t go = (i0 + row) * 1024 + kv0 + kc * 8;
            CP16(sb + sw, Ah + go);
            CP16(sb + 16384 + sw, Al + go);
            CP16(sb + 32768 + sw, Bh + (j0 + row) * 1024 + kv0 + kc * 8);
        }
    };

    load_stage(0, 0); CP_COMMIT();
    load_stage(1, 1); CP_COMMIT();

    for (int st = 0; st < 16; ++st) {
        CP_WAIT1();
        __syncthreads();
        const int buf = st & 1;
        const uint32_t sb = sbase + buf * STAGE_B0;
#pragma unroll
        for (int kk = 0; kk < 4; kk++) {
            uint32_t ah[4][4], al[4][4];
#pragma unroll
            for (int mt = 0; mt < 4; mt++) {
                uint32_t addr = sb + (arow + mt * 16) * 128 + (((kk * 2 + a_cs) ^ a_x7) << 4);
                LDSM4(ah[mt], addr);
                LDSM4(al[mt], addr + 16384);
            }
#pragma unroll
            for (int nt2 = 0; nt2 < 2; nt2++) {
                uint32_t bh[4];
                LDSM4(bh, sb + 32768 + (brow + nt2 * 16) * 128 +
                          (((kk * 2 + b_cs) ^ b_x7) << 4));
#pragma unroll
                for (int mt = 0; mt < 4; mt++) {
                    MMAH(acc[mt][nt2 * 2],     ah[mt], bh[0], bh[1]);
                    MMAH(acc[mt][nt2 * 2 + 1], ah[mt], bh[2], bh[3]);
                    MMAH(acc[mt][nt2 * 2],     al[mt], bh[0], bh[1]);
                    MMAH(acc[mt][nt2 * 2 + 1], al[mt], bh[2], bh[3]);
                }
            }
        }
        __syncthreads();
        if (st + 2 < 16) load_stage(st + 2, buf);
        CP_COMMIT();
    }

    const int crow = lane >> 2;
    const int ccol = (lane & 3) * 2;
    __half* C = g_Abf_h + (size_t)(s * 2048 + 1024) * 1024;
#pragma unroll
    for (int mt = 0; mt < 4; mt++) {
        size_t rbase = (i0 + wm + mt * 16 + crow) * 1024 + j0 + wn + ccol;
#pragma unroll
        for (int nt = 0; nt < 4; nt++) {
            __half* p = C + rbase + nt * 8;
            *(__half2*)p              = __floats2half2_rn(acc[mt][nt][0], acc[mt][nt][1]);
            *(__half2*)(p + 8 * 1024) = __floats2half2_rn(acc[mt][nt][2], acc[mt][nt][3]);
        }
    }
}

// ---------------- gemm1: diffusion 1-term, BM=128 BN=128, 3-stage, 2 CTAs/SM ----------------
// half = 0: first-order rows; half = 1: squared rows. jof = first j-tile of group.
#define STAGE_B1 32768
#define GEMM_DYN1 (3 * STAGE_B1)

__global__ __launch_bounds__(256, 2) void k_gemm1(int half, int jof) {
    extern __shared__ char sm[];
    const uint32_t sbase = smem_u32(sm);
    const int tid = threadIdx.x, lane = tid & 31, wid = tid >> 5;

    const size_t i0 = (size_t)(((blockIdx.x >> 3) * 16) + half * 8 + (blockIdx.x & 7)) * 128;
    const size_t j0 = (size_t)(jof + blockIdx.y) * 128;

    const int wm = (wid & 1) * 64;
    const int wn = (wid >> 1) * 32;
    const int arow = wm + (lane & 15);
    const int a_x7 = arow & 7;
    const int a_cs = lane >> 4;
    const int brow = wn + ((lane >> 4) << 3) + (lane & 7);
    const int b_x7 = brow & 7;
    const int b_cs = (lane >> 3) & 1;

    float acc[4][4][4];
#pragma unroll
    for (int mt = 0; mt < 4; mt++)
#pragma unroll
        for (int nt = 0; nt < 4; nt++)
#pragma unroll
            for (int q = 0; q < 4; q++) acc[mt][nt][q] = 0.f;

    auto load_stage = [&](int st, int buf) {
        const int kv0 = st * 64;
        const uint32_t sb = sbase + buf * STAGE_B1;
#pragma unroll
        for (int q = 0; q < 4; q++) {
            int id = tid + 256 * q;
            int row = id >> 3, kc = id & 7;
            uint32_t sw = row * 128 + ((kc ^ (row & 7)) << 4);
            CP16(sb + sw, g_Abf_h + (i0 + row) * 1024 + kv0 + kc * 8);
        }
#pragma unroll
        for (int q = 0; q < 4; q++) {
            int id = tid + 256 * q;
            int row = id >> 3, kc = id & 7;
            uint32_t sw = row * 128 + ((kc ^ (row & 7)) << 4);
            CP16(sb + 16384 + sw, g_Xh + (j0 + row) * 1024 + kv0 + kc * 8);
        }
    };

    load_stage(0, 0); CP_COMMIT();
    load_stage(1, 1); CP_COMMIT();
    load_stage(2, 2); CP_COMMIT();

    int buf = 0;
    for (int st = 0; st < 16; ++st) {
        CP_WAIT2();
        __syncthreads();
        const uint32_t sb = sbase + buf * STAGE_B1;
#pragma unroll
        for (int kk = 0; kk < 4; kk++) {
            uint32_t ah[4][4];
#pragma unroll
            for (int mt = 0; mt < 4; mt++)
                LDSM4(ah[mt], sb + (arow + mt * 16) * 128 + (((kk * 2 + a_cs) ^ a_x7) << 4));
#pragma unroll
            for (int nt2 = 0; nt2 < 2; nt2++) {
                uint32_t bh[4];
                LDSM4(bh, sb + 16384 + (brow + nt2 * 16) * 128 +
                          (((kk * 2 + b_cs) ^ b_x7) << 4));
#pragma unroll
                for (int mt = 0; mt < 4; mt++) {
                    MMAH(acc[mt][nt2 * 2],     ah[mt], bh[0], bh[1]);
                    MMAH(acc[mt][nt2 * 2 + 1], ah[mt], bh[2], bh[3]);
                }
            }
        }
        __syncthreads();
        if (st + 3 < 16) load_stage(st + 3, buf);
        CP_COMMIT();
        buf = (buf + 1 == 3) ? 0 : buf + 1;
    }

    const int crow = lane >> 2;
    const int ccol = (lane & 3) * 2;
#pragma unroll
    for (int mt = 0; mt < 4; mt++) {
        size_t rbase = (i0 + wm + mt * 16 + crow) * MCOLS + j0 + wn + ccol;
#pragma unroll
        for (int nt = 0; nt < 4; nt++) {
            __half* p = g_yt + rbase + nt * 8;
            *(__half2*)p               = __floats2half2_rn(acc[mt][nt][0], acc[mt][nt][1]);
            *(__half2*)(p + 8 * MCOLS) = __floats2half2_rn(acc[mt][nt][2], acc[mt][nt][3]);
        }
    }
}

// ---------------- final MMA: out = Wh * H + bias, per-batch-group ----------------
#define FIN_W    0
#define FIN_HS   (64 * PAD_E * 2)
#define FIN_DYN  (FIN_HS + 128 * PAD_E * 2)

__global__ __launch_bounds__(256, 2) void k_final(const float* __restrict__ bias,
                                                  float* __restrict__ out, int bof) {
    extern __shared__ char sm[];
    const uint32_t sbase = smem_u32(sm);
    const int tid = threadIdx.x, lane = tid & 31, wid = tid >> 5;
    const int b = bof + blockIdx.y;
    const int j0 = blockIdx.x * 128;

    for (int e = tid; e < 64 * 28; e += 256) {
        int r = e / 28, q = e - r * 28;
        CP16(sbase + FIN_W + r * 464 + q * 16, g_Wh + r * CIN + q * 8);
    }
    for (int e = tid; e < 128 * 14; e += 256) {
        int r = e / 14, q = e - r * 14;
        int n = j0 + r;
        int v = n / 13, l = n - v * 13;
        const __half* src;
        if (q < 4)
            src = g_Xt + ((size_t)b * MCOLS + n) * 32 + q * 8;
        else {
            int g = (q - 4) >> 2, ch = (q - 4) & 3;
            src = g_yt + ((size_t)(g * 1024 + v)) * MCOLS + b * 416 + l * 32 + ch * 8;
        }
        CP16(sbase + FIN_HS + r * 464 + q * 16, src);
    }
    CP_COMMIT();
    for (int e = tid; e < 128 * 14; e += 256) {
        int r = e / 14, q = 14 + (e - r * 14);
        int n = j0 + r;
        int v = n / 13, l = n - v * 13;
        int g = (q - 4) >> 2, ch = (q - 4) & 3;
        const __half* src = g_yt + ((size_t)(g * 1024 + v)) * MCOLS + b * 416 + l * 32 + ch * 8;
        CP16(sbase + FIN_HS + r * 464 + q * 16, src);
    }
    CP_COMMIT();

    const int wm = (wid & 1) * 32;
    const int wn = (wid >> 1) * 32;
    const int arow_l = lane & 15;
    const int a_cs = lane >> 4;
    const int brow_l = ((lane >> 4) << 3) + (lane & 7);
    const int b_cs = (lane >> 3) & 1;

    float acc[2][4][4];
#pragma unroll
    for (int mt = 0; mt < 2; mt++)
#pragma unroll
        for (int nt = 0; nt < 4; nt++)
#pragma unroll
            for (int q = 0; q < 4; q++) acc[mt][nt][q] = 0.f;

    CP_WAIT1();
    __syncthreads();

#pragma unroll
    for (int kc = 0; kc < 7; kc++) {
        uint32_t wh[2][4];
#pragma unroll
        for (int mt = 0; mt < 2; mt++)
            LDSM4(wh[mt], sbase + FIN_W + (wm + mt * 16 + arow_l) * 464 + (kc * 2 + a_cs) * 16);
#pragma unroll
        for (int nt2 = 0; nt2 < 2; nt2++) {
            uint32_t bh[4];
            LDSM4(bh, sbase + FIN_HS + (wn + nt2 * 16 + brow_l) * 464 +
                      (kc * 2 + b_cs) * 16);
#pragma unroll
            for (int mt = 0; mt < 2; mt++) {
                MMAH(acc[mt][nt2 * 2],     wh[mt], bh[0], bh[1]);
                MMAH(acc[mt][nt2 * 2 + 1], wh[mt], bh[2], bh[3]);
            }
        }
    }

    CP_WAIT0();
    __syncthreads();

#pragma unroll
    for (int kc = 7; kc < 14; kc++) {
        uint32_t wh[2][4];
#pragma unroll
        for (int mt = 0; mt < 2; mt++)
            LDSM4(wh[mt], sbase + FIN_W + (wm + mt * 16 + arow_l) * 464 + (kc * 2 + a_cs) * 16);
#pragma unroll
        for (int nt2 = 0; nt2 < 2; nt2++) {
            uint32_t bh[4];
            LDSM4(bh, sbase + FIN_HS + (wn + nt2 * 16 + brow_l) * 464 +
                      (kc * 2 + b_cs) * 16);
#pragma unroll
            for (int mt = 0; mt < 2; mt++) {
                MMAH(acc[mt][nt2 * 2],     wh[mt], bh[0], bh[1]);
                MMAH(acc[mt][nt2 * 2 + 1], wh[mt], bh[2], bh[3]);
            }
        }
    }

    const int crow = lane >> 2;
    const int ccol = (lane & 3) * 2;
#pragma unroll
    for (int mt = 0; mt < 2; mt++) {
        int o = wm + mt * 16 + crow;
        float b0 = bias[o], b1 = bias[o + 8];
        size_t r0 = (size_t)(b * 64 + o) * MCOLS + j0 + wn + ccol;
#pragma unroll
        for (int nt = 0; nt < 4; nt++) {
            float* p = out + r0 + nt * 8;
            *(float2*)p               = make_float2(acc[mt][nt][0] + b0, acc[mt][nt][1] + b0);
            *(float2*)(p + 8 * MCOLS) = make_float2(acc[mt][nt][2] + b1, acc[mt][nt][3] + b1);
        }
    }
}

// ---------------- launcher: 3-stream pipelined fork-join ----------------
#define NGRP 8

extern "C" void kernel_launch(void* const* d_in, const int* in_sizes, int n_in,
                              void* d_out, int out_size) {
    const float* x    = (const float*)d_in[0];
    const float* A0   = (const float*)d_in[1];
    const float* A1   = (const float*)d_in[2];
    const float* A2   = (const float*)d_in[3];
    const float* W    = (const float*)d_in[4];
    const float* bias = (const float*)d_in[5];
    float* out = (float*)d_out;

    static cudaStream_t s2 = nullptr, s3 = nullptr;
    static cudaEvent_t e0, eA, eX, eF2, eF3;
    static cudaEvent_t ea[NGRP], eb[NGRP];
    if (!s2) {
        int loPri, hiPri;
        cudaDeviceGetStreamPriorityRange(&loPri, &hiPri);
        cudaStreamCreateWithFlags(&s2, cudaStreamNonBlocking);
        cudaStreamCreateWithPriority(&s3, cudaStreamNonBlocking, hiPri);
        cudaEventCreateWithFlags(&e0, cudaEventDisableTiming);
        cudaEventCreateWithFlags(&eA, cudaEventDisableTiming);
        cudaEventCreateWithFlags(&eX, cudaEventDisableTiming);
        cudaEventCreateWithFlags(&eF2, cudaEventDisableTiming);
        cudaEventCreateWithFlags(&eF3, cudaEventDisableTiming);
        for (int g = 0; g < NGRP; g++) {
            cudaEventCreateWithFlags(&ea[g], cudaEventDisableTiming);
            cudaEventCreateWithFlags(&eb[g], cudaEventDisableTiming);
        }
        cudaFuncSetAttribute(k_gemm0, cudaFuncAttributeMaxDynamicSharedMemorySize, GEMM_DYN0);
        cudaFuncSetAttribute(k_gemm1, cudaFuncAttributeMaxDynamicSharedMemorySize, GEMM_DYN1);
        cudaFuncSetAttribute(k_final, cudaFuncAttributeMaxDynamicSharedMemorySize, FIN_DYN);
    }

    // fork
    cudaEventRecord(e0, 0);
    cudaStreamWaitEvent(s2, e0, 0);
    cudaStreamWaitEvent(s3, e0, 0);

    // s2: X staging (g_Xh + g_Xt); eX recorded immediately after
    k_stageX<<<dim3(64, 32), 256, 0, s2>>>(x);
    cudaEventRecord(eX, s2);

    // s3: W convert (only consumer is k_final, in-order on s3)
    k_convW<<<56, 256, 0, s3>>>(W);

    // stream 0: A staging, then gemm0 (96KB, co-resident)
    k_stageA<<<dim3(32, 32, 3), dim3(32, 8)>>>(A0, A1, A2);
    cudaEventRecord(eA, 0);
    k_gemm0<<<dim3(8, 8, 3), 256, GEMM_DYN0>>>();

    // s2: gemm1a groups (need stageA; stageX in-order on s2)
    cudaStreamWaitEvent(s2, eA, 0);
    for (int g = 0; g < NGRP; g++) {
        k_gemm1<<<dim3(24, 13), 256, GEMM_DYN1, s2>>>(0, g * 13);
        cudaEventRecord(ea[g], s2);
    }
    cudaEventRecord(eF2, s2);

    // stream 0: gemm1b groups (after gemm0 in-order; need stageX for g_Xh)
    cudaStreamWaitEvent(0, eX, 0);
    for (int g = 0; g < NGRP; g++) {
        k_gemm1<<<dim3(24, 13), 256, GEMM_DYN1>>>(1, g * 13);
        cudaEventRecord(eb[g], 0);
    }

    // s3 (high priority): k_final groups as their columns complete
    cudaStreamWaitEvent(s3, eX, 0);
    for (int g = 0; g < NGRP; g++) {
        cudaStreamWaitEvent(s3, ea[g], 0);
        cudaStreamWaitEvent(s3, eb[g], 0);
        k_final<<<dim3(104, 4), 256, FIN_DYN, s3>>>(bias, out, g * 4);
    }
    cudaEventRecord(eF3, s3);

    // join back to stream 0
    cudaStreamWaitEvent(0, eF2, 0);
    cudaStreamWaitEvent(0, eF3, 0);
}